// round 10
// baseline (speedup 1.0000x reference)
#include <cuda_runtime.h>
#include <cuda_bf16.h>
#include <cstdint>

// ---------------------------------------------------------------------------
// Problem constants
// ---------------------------------------------------------------------------
#define DIM   512
#define NNODE 65536
#define MMUT  32768

// ---------------------------------------------------------------------------
// Smem tile geometry: CTA tile 128x128, K-stage 32, rows padded to 40 bf16
// ---------------------------------------------------------------------------
#define RS      40                    // row stride in bf16 (80 bytes)
#define MAT_ELE (128 * RS)            // one 128x32(+pad) matrix = 5120 bf16
#define BUF_ELE (4 * MAT_ELE)         // A_hi, A_lo, B_hi, B_lo
#define BUF_BYTES (BUF_ELE * 2)       // 40960
#define SMEM_BYTES (2 * BUF_BYTES)    // double buffered = 81920 B

#define DI __device__ __forceinline__

// ---------------------------------------------------------------------------
// Device scratch (__device__ globals only — no allocations)
// ---------------------------------------------------------------------------
__device__ __nv_bfloat16 g_wo_hi[DIM * DIM];
__device__ __nv_bfloat16 g_wo_lo[DIM * DIM];
__device__ __nv_bfloat16 g_wc_hi[DIM * DIM];
__device__ __nv_bfloat16 g_wc_lo[DIM * DIM];
__device__ __nv_bfloat16 g_lin_hi[DIM * 2 * DIM];
__device__ __nv_bfloat16 g_lin_lo[DIM * 2 * DIM];
// pre-split inputs: h_p, h_k as bf16 hi/lo
__device__ __nv_bfloat16 g_hp_hi[(size_t)NNODE * DIM];
__device__ __nv_bfloat16 g_hp_lo[(size_t)NNODE * DIM];
__device__ __nv_bfloat16 g_hk_hi[(size_t)NNODE * DIM];
__device__ __nv_bfloat16 g_hk_lo[(size_t)NNODE * DIM];
// gathered + tanh'd + split GEMM2 A matrix: [MMUT, 1024] bf16 hi/lo
__device__ __nv_bfloat16 g_gh[(size_t)MMUT * 2 * DIM];
__device__ __nv_bfloat16 g_gl[(size_t)MMUT * 2 * DIM];

// ---------------------------------------------------------------------------
// Helpers
// ---------------------------------------------------------------------------
DI uint32_t smem_u32(const void* p) {
    uint32_t a;
    asm("{ .reg .u64 t; cvta.to.shared.u64 t, %1; cvt.u32.u64 %0, t; }"
        : "=r"(a) : "l"(p));
    return a;
}

DI void split_bf16(float v, __nv_bfloat16& h, __nv_bfloat16& l) {
    h = __float2bfloat16(v);
    l = __float2bfloat16(v - __bfloat162float(h));
}

DI void ldsm_x4(uint32_t* r, uint32_t addr) {
    asm volatile("ldmatrix.sync.aligned.m8n8.x4.shared.b16 {%0,%1,%2,%3}, [%4];"
                 : "=r"(r[0]), "=r"(r[1]), "=r"(r[2]), "=r"(r[3]) : "r"(addr));
}

DI void mma_bf16(float* c, const uint32_t* a, uint32_t b0, uint32_t b1) {
    asm volatile(
        "mma.sync.aligned.m16n8k16.row.col.f32.bf16.bf16.f32 "
        "{%0,%1,%2,%3}, {%4,%5,%6,%7}, {%8,%9}, {%0,%1,%2,%3};"
        : "+f"(c[0]), "+f"(c[1]), "+f"(c[2]), "+f"(c[3])
        : "r"(a[0]), "r"(a[1]), "r"(a[2]), "r"(a[3]), "r"(b0), "r"(b1));
}

DI void cp_async16(uint32_t saddr, const void* gptr) {
    asm volatile("cp.async.cg.shared.global [%0], [%1], 16;"
                 :: "r"(saddr), "l"(gptr));
}
DI void cp_commit() { asm volatile("cp.async.commit_group;" ::: "memory"); }
template <int N> DI void cp_wait() {
    asm volatile("cp.async.wait_group %0;" :: "n"(N) : "memory");
}

// ---------------------------------------------------------------------------
// One K-stage (32) of the split-bf16 warp-tile MMA.
// Warp tile 64x64 (4 warps per CTA, 2x2): 32 ldsm.x4 feed 192 HMMAs per stage
// (6 MMA/ldsm). Product-major issue: 8 independent accumulators per run.
// ---------------------------------------------------------------------------
DI void compute_stage(uint32_t base, int lane, int wm, int wn,
                      float acc[4][8][4]) {
    const uint32_t sAhi = base;
    const uint32_t sAlo = base + MAT_ELE * 2;
    const uint32_t sBhi = base + MAT_ELE * 4;
    const uint32_t sBlo = base + MAT_ELE * 6;
    const int lrow = lane & 15;
    const int lkh  = lane >> 4;
#pragma unroll
    for (int ks = 0; ks < 2; ++ks) {
        const uint32_t kbyte = (uint32_t)(ks * 16 + 8 * lkh) * 2;
        uint32_t ah[4][4], al[4][4];
#pragma unroll
        for (int mt = 0; mt < 4; ++mt) {
            uint32_t off = (uint32_t)((wm * 64 + mt * 16 + lrow) * (RS * 2)) + kbyte;
            ldsm_x4(ah[mt], sAhi + off);
            ldsm_x4(al[mt], sAlo + off);
        }
#pragma unroll
        for (int np = 0; np < 4; ++np) {
            uint32_t off = (uint32_t)((wn * 64 + np * 16 + lrow) * (RS * 2)) + kbyte;
            uint32_t bh[4], bl[4];
            ldsm_x4(bh, sBhi + off);
            ldsm_x4(bl, sBlo + off);
            // product-major: 8 independent HMMAs per class before acc reuse
#pragma unroll
            for (int mt = 0; mt < 4; ++mt)
#pragma unroll
                for (int w = 0; w < 2; ++w)
                    mma_bf16(acc[mt][np * 2 + w], ah[mt], bh[w], bh[w + 2]);
#pragma unroll
            for (int mt = 0; mt < 4; ++mt)
#pragma unroll
                for (int w = 0; w < 2; ++w)
                    mma_bf16(acc[mt][np * 2 + w], al[mt], bh[w], bh[w + 2]);
#pragma unroll
            for (int mt = 0; mt < 4; ++mt)
#pragma unroll
                for (int w = 0; w < 2; ++w)
                    mma_bf16(acc[mt][np * 2 + w], ah[mt], bl[w], bl[w + 2]);
        }
    }
}

// ---------------------------------------------------------------------------
// cp.async one stage: 4 matrices x 128 rows x 64B with 128 threads
// (16 chunks of 16B per thread)
// ---------------------------------------------------------------------------
DI void stage_cp(uint32_t sbase,
                 const __nv_bfloat16* Ah, const __nv_bfloat16* Al,
                 const __nv_bfloat16* Bh, const __nv_bfloat16* Bl,
                 int ldA, int ldB, int m0, int n0, int k0, int tid) {
    const int q = tid & 3;        // 16B chunk within 64B row
    const int r = tid >> 2;       // 0..31
#pragma unroll
    for (int i = 0; i < 16; ++i) {
        const int mat = i >> 2;                   // 0:A_hi 1:A_lo 2:B_hi 3:B_lo
        const int row = (i & 3) * 32 + r;
        const __nv_bfloat16* p = (mat == 0) ? Ah : (mat == 1) ? Al
                               : (mat == 2) ? Bh : Bl;
        const int ld = (mat < 2) ? ldA : ldB;
        const int r0 = (mat < 2) ? m0 : n0;
        uint32_t sa = sbase + (uint32_t)(mat * (MAT_ELE * 2) + row * (RS * 2) + q * 16);
        cp_async16(sa, p + (size_t)(r0 + row) * ld + k0 + q * 8);
    }
}

// ---------------------------------------------------------------------------
// prep: split weights to bf16 hi/lo (+ transpose W_o, W_c to [n][k])
// ---------------------------------------------------------------------------
__global__ void prep_kernel(const float* __restrict__ wo, const float* __restrict__ wc,
                            const float* __restrict__ lw) {
    int i = blockIdx.x * 256 + threadIdx.x;   // 0 .. 512*1024-1
    int n = i >> 10;
    int k = i & 1023;

    __nv_bfloat16 h, l;
    split_bf16(lw[i], h, l);                  // lin_w is [512][1024] = [n][k]
    g_lin_hi[i] = h;
    g_lin_lo[i] = l;

    if (k < 512) {
        int src = k * 512 + n;                // B[n][k] = W[k][n]
        int dst = n * 512 + k;
        split_bf16(wo[src], h, l);
        g_wo_hi[dst] = h; g_wo_lo[dst] = l;
        split_bf16(wc[src], h, l);
        g_wc_hi[dst] = h; g_wc_lo[dst] = l;
    }
}

// ---------------------------------------------------------------------------
// split inputs: h_p, h_k fp32 -> bf16 hi/lo  (pure bandwidth pass)
// ---------------------------------------------------------------------------
__global__ void split_inputs_kernel(const float* __restrict__ hp,
                                    const float* __restrict__ hk) {
    const size_t idx = (size_t)blockIdx.x * 256 + threadIdx.x;   // float4 index
    const int z = blockIdx.y;
    const float* src = z ? hk : hp;
    __nv_bfloat16* dh = z ? g_hk_hi : g_hp_hi;
    __nv_bfloat16* dl = z ? g_hk_lo : g_hp_lo;

    float4 v = *reinterpret_cast<const float4*>(src + idx * 4);
    __nv_bfloat16 h0, l0, h1, l1, h2, l2, h3, l3;
    split_bf16(v.x, h0, l0);
    split_bf16(v.y, h1, l1);
    split_bf16(v.z, h2, l2);
    split_bf16(v.w, h3, l3);
    __nv_bfloat162 ph0; ph0.x = h0; ph0.y = h1;
    __nv_bfloat162 ph1; ph1.x = h2; ph1.y = h3;
    __nv_bfloat162 pl0; pl0.x = l0; pl0.y = l1;
    __nv_bfloat162 pl1; pl1.x = l2; pl1.y = l3;
    uint2 uh; uh.x = *reinterpret_cast<uint32_t*>(&ph0); uh.y = *reinterpret_cast<uint32_t*>(&ph1);
    uint2 ul; ul.x = *reinterpret_cast<uint32_t*>(&pl0); ul.y = *reinterpret_cast<uint32_t*>(&pl1);
    *reinterpret_cast<uint2*>(dh + idx * 4) = uh;
    *reinterpret_cast<uint2*>(dl + idx * 4) = ul;
}

// ---------------------------------------------------------------------------
// GEMM1: trans_hp = h_p @ W_o ; trans_hk = h_k @ W_c   (all operands pre-split)
// grid (4 n-tiles, 512 m-tiles, 2), block 128 (4 warps, 2x2), 2 CTAs/SM
// ---------------------------------------------------------------------------
__global__ __launch_bounds__(128, 2) void gemm1_kernel(float* __restrict__ out) {
    extern __shared__ __align__(16) __nv_bfloat16 sm[];
    const int tid = threadIdx.x, lane = tid & 31, wid = tid >> 5;
    const int wm = wid & 1, wn = wid >> 1;
    const int n0 = blockIdx.x * 128, m0 = blockIdx.y * 128, z = blockIdx.z;

    const __nv_bfloat16* Ah = z ? g_hk_hi : g_hp_hi;
    const __nv_bfloat16* Al = z ? g_hk_lo : g_hp_lo;
    const __nv_bfloat16* Bh = z ? g_wc_hi : g_wo_hi;
    const __nv_bfloat16* Bl = z ? g_wc_lo : g_wo_lo;
    float* dst = out + (size_t)z * NNODE * DIM;

    float acc[4][8][4];
#pragma unroll
    for (int i = 0; i < 4; ++i)
#pragma unroll
        for (int j = 0; j < 8; ++j)
#pragma unroll
            for (int k = 0; k < 4; ++k) acc[i][j][k] = 0.f;

    const uint32_t sb = smem_u32(sm);

    stage_cp(sb, Ah, Al, Bh, Bl, DIM, DIM, m0, n0, 0, tid);
    cp_commit();

    const int S = DIM / 32;   // 16 stages
#pragma unroll 1
    for (int s = 0; s < S; ++s) {
        if (s + 1 < S) {
            stage_cp(sb + ((s + 1) & 1) * BUF_BYTES, Ah, Al, Bh, Bl,
                     DIM, DIM, m0, n0, (s + 1) * 32, tid);
            cp_commit();
            cp_wait<1>();
        } else {
            cp_wait<0>();
        }
        __syncthreads();
        compute_stage(sb + (s & 1) * BUF_BYTES, lane, wm, wn, acc);
        __syncthreads();
    }

#pragma unroll
    for (int mt = 0; mt < 4; ++mt) {
        int grow = m0 + wm * 64 + mt * 16 + (lane >> 2);
#pragma unroll
        for (int nt = 0; nt < 8; ++nt) {
            int gcol = n0 + wn * 64 + nt * 8 + (lane & 3) * 2;
            float2 v0; v0.x = acc[mt][nt][0]; v0.y = acc[mt][nt][1];
            float2 v1; v1.x = acc[mt][nt][2]; v1.y = acc[mt][nt][3];
            *reinterpret_cast<float2*>(dst + (size_t)grow * DIM + gcol) = v0;
            *reinterpret_cast<float2*>(dst + (size_t)(grow + 8) * DIM + gcol) = v1;
        }
    }
}

// ---------------------------------------------------------------------------
// gather + tanh + bf16 split
// ---------------------------------------------------------------------------
__global__ void gather_tanh_kernel(const float* __restrict__ out,
                                   const int* __restrict__ idxp,
                                   const int* __restrict__ idxk) {
    const int m = blockIdx.x;
    const int t = threadIdx.x;                 // 256 threads, 2 cols each half
    const float* outp = out;
    const float* outk = out + (size_t)NNODE * DIM;
    const int rp = idxp[m], rk = idxk[m];

    float2 v = *reinterpret_cast<const float2*>(outp + (size_t)rp * DIM + 2 * t);
    float2 w = *reinterpret_cast<const float2*>(outk + (size_t)rk * DIM + 2 * t);

    __nv_bfloat16 h0, l0, h1, l1;
    size_t base = (size_t)m * (2 * DIM);

    split_bf16(tanhf(v.x), h0, l0);
    split_bf16(tanhf(v.y), h1, l1);
    __nv_bfloat162 ph; ph.x = h0; ph.y = h1;
    __nv_bfloat162 pl; pl.x = l0; pl.y = l1;
    *reinterpret_cast<__nv_bfloat162*>(g_gh + base + 2 * t) = ph;
    *reinterpret_cast<__nv_bfloat162*>(g_gl + base + 2 * t) = pl;

    split_bf16(tanhf(w.x), h0, l0);
    split_bf16(tanhf(w.y), h1, l1);
    ph.x = h0; ph.y = h1;
    pl.x = l0; pl.y = l1;
    *reinterpret_cast<__nv_bfloat162*>(g_gh + base + DIM + 2 * t) = ph;
    *reinterpret_cast<__nv_bfloat162*>(g_gl + base + DIM + 2 * t) = pl;
}

// ---------------------------------------------------------------------------
// GEMM2: rows = leaky_relu(g @ lin_w^T + lin_b) + bias, scattered into both
//        halves of d_out.  grid (4, 256), block 128 (4 warps), 2 CTAs/SM
// ---------------------------------------------------------------------------
__global__ __launch_bounds__(128, 2) void gemm2_kernel(
    const int* __restrict__ idxp, const int* __restrict__ idxk,
    const float* __restrict__ lin_b, const float* __restrict__ bias,
    float* __restrict__ out) {
    extern __shared__ __align__(16) __nv_bfloat16 sm[];
    const int tid = threadIdx.x, lane = tid & 31, wid = tid >> 5;
    const int wm = wid & 1, wn = wid >> 1;
    const int n0 = blockIdx.x * 128, m0 = blockIdx.y * 128;

    float* outp = out;
    float* outk = out + (size_t)NNODE * DIM;

    float acc[4][8][4];
#pragma unroll
    for (int i = 0; i < 4; ++i)
#pragma unroll
        for (int j = 0; j < 8; ++j)
#pragma unroll
            for (int k = 0; k < 4; ++k) acc[i][j][k] = 0.f;

    const uint32_t sb = smem_u32(sm);

    stage_cp(sb, g_gh, g_gl, g_lin_hi, g_lin_lo, 2 * DIM, 2 * DIM, m0, n0, 0, tid);
    cp_commit();

    const int S = (2 * DIM) / 32;   // 32 stages
#pragma unroll 1
    for (int s = 0; s < S; ++s) {
        if (s + 1 < S) {
            stage_cp(sb + ((s + 1) & 1) * BUF_BYTES, g_gh, g_gl, g_lin_hi, g_lin_lo,
                     2 * DIM, 2 * DIM, m0, n0, (s + 1) * 32, tid);
            cp_commit();
            cp_wait<1>();
        } else {
            cp_wait<0>();
        }
        __syncthreads();
        compute_stage(sb + (s & 1) * BUF_BYTES, lane, wm, wn, acc);
        __syncthreads();
    }

#pragma unroll
    for (int mt = 0; mt < 4; ++mt) {
        int grow = m0 + wm * 64 + mt * 16 + (lane >> 2);
        int p0 = idxp[grow], p1 = idxp[grow + 8];
        int q0 = idxk[grow], q1 = idxk[grow + 8];
#pragma unroll
        for (int nt = 0; nt < 8; ++nt) {
            int gcol = n0 + wn * 64 + nt * 8 + (lane & 3) * 2;
            float2 lb = *reinterpret_cast<const float2*>(lin_b + gcol);
            float2 bs = *reinterpret_cast<const float2*>(bias + gcol);
            float x0 = acc[mt][nt][0] + lb.x;
            float x1 = acc[mt][nt][1] + lb.y;
            float x2 = acc[mt][nt][2] + lb.x;
            float x3 = acc[mt][nt][3] + lb.y;
            x0 = (x0 >= 0.f ? x0 : 0.01f * x0) + bs.x;
            x1 = (x1 >= 0.f ? x1 : 0.01f * x1) + bs.y;
            x2 = (x2 >= 0.f ? x2 : 0.01f * x2) + bs.x;
            x3 = (x3 >= 0.f ? x3 : 0.01f * x3) + bs.y;
            float2 v0; v0.x = x0; v0.y = x1;
            float2 v1; v1.x = x2; v1.y = x3;
            *reinterpret_cast<float2*>(outp + (size_t)p0 * DIM + gcol) = v0;
            *reinterpret_cast<float2*>(outp + (size_t)p1 * DIM + gcol) = v1;
            *reinterpret_cast<float2*>(outk + (size_t)q0 * DIM + gcol) = v0;
            *reinterpret_cast<float2*>(outk + (size_t)q1 * DIM + gcol) = v1;
        }
    }
}

// ---------------------------------------------------------------------------
// Launch
// ---------------------------------------------------------------------------
extern "C" void kernel_launch(void* const* d_in, const int* in_sizes, int n_in,
                              void* d_out, int out_size) {
    const float* h_p  = (const float*)d_in[0];
    const float* h_k  = (const float*)d_in[1];
    const int*   idxp = (const int*)d_in[2];
    const int*   idxk = (const int*)d_in[3];
    // d_in[4] = last_x (unused by the reference computation)
    const float* wo   = (const float*)d_in[5];
    const float* wc   = (const float*)d_in[6];
    const float* lw   = (const float*)d_in[7];
    const float* lb   = (const float*)d_in[8];
    const float* bias = (const float*)d_in[9];
    float* out = (float*)d_out;

    cudaFuncSetAttribute(gemm1_kernel, cudaFuncAttributeMaxDynamicSharedMemorySize, SMEM_BYTES);
    cudaFuncSetAttribute(gemm2_kernel, cudaFuncAttributeMaxDynamicSharedMemorySize, SMEM_BYTES);

    prep_kernel<<<(512 * 1024) / 256, 256>>>(wo, wc, lw);

    split_inputs_kernel<<<dim3((NNODE * DIM / 4) / 256, 2), 256>>>(h_p, h_k);

    gemm1_kernel<<<dim3(DIM / 128, NNODE / 128, 2), 128, SMEM_BYTES>>>(out);

    gather_tanh_kernel<<<MMUT, 256>>>(out, idxp, idxk);

    gemm2_kernel<<<dim3(DIM / 128, MMUT / 128), 128, SMEM_BYTES>>>(idxp, idxk, lb, bias, out);
}

// round 11
// speedup vs baseline: 1.0288x; 1.0288x over previous
#include <cuda_runtime.h>
#include <cuda_bf16.h>
#include <cstdint>

// ---------------------------------------------------------------------------
// Problem constants
// ---------------------------------------------------------------------------
#define DIM   512
#define NNODE 65536
#define MMUT  32768

// ---------------------------------------------------------------------------
// Smem tile geometry: CTA tile 128x128, K-stage 32, rows padded to 40 bf16
// ---------------------------------------------------------------------------
#define RS      40                    // row stride in bf16 (80 bytes)
#define MAT_ELE (128 * RS)            // one 128x32(+pad) matrix = 5120 bf16
#define BUF_ELE (4 * MAT_ELE)         // A_hi, A_lo, B_hi, B_lo
#define BUF_BYTES (BUF_ELE * 2)       // 40960
#define SMEM_BYTES (2 * BUF_BYTES)    // double buffered = 81920 B

#define DI __device__ __forceinline__

// ---------------------------------------------------------------------------
// Device scratch (__device__ globals only — no allocations)
// ---------------------------------------------------------------------------
__device__ __nv_bfloat16 g_wo_hi[DIM * DIM];
__device__ __nv_bfloat16 g_wo_lo[DIM * DIM];
__device__ __nv_bfloat16 g_wc_hi[DIM * DIM];
__device__ __nv_bfloat16 g_wc_lo[DIM * DIM];
__device__ __nv_bfloat16 g_lin_hi[DIM * 2 * DIM];
__device__ __nv_bfloat16 g_lin_lo[DIM * 2 * DIM];
// pre-split inputs: h_p, h_k as bf16 hi/lo
__device__ __nv_bfloat16 g_hp_hi[(size_t)NNODE * DIM];
__device__ __nv_bfloat16 g_hp_lo[(size_t)NNODE * DIM];
__device__ __nv_bfloat16 g_hk_hi[(size_t)NNODE * DIM];
__device__ __nv_bfloat16 g_hk_lo[(size_t)NNODE * DIM];
// gathered + tanh'd + split GEMM2 A matrix: [MMUT, 1024] bf16 hi/lo
__device__ __nv_bfloat16 g_gh[(size_t)MMUT * 2 * DIM];
__device__ __nv_bfloat16 g_gl[(size_t)MMUT * 2 * DIM];
// inverse index maps: node -> mutual position (or -1)
__device__ int g_inv_p[NNODE];
__device__ int g_inv_k[NNODE];

// ---------------------------------------------------------------------------
// Helpers
// ---------------------------------------------------------------------------
DI uint32_t smem_u32(const void* p) {
    uint32_t a;
    asm("{ .reg .u64 t; cvta.to.shared.u64 t, %1; cvt.u32.u64 %0, t; }"
        : "=r"(a) : "l"(p));
    return a;
}

DI void split_bf16(float v, __nv_bfloat16& h, __nv_bfloat16& l) {
    h = __float2bfloat16(v);
    l = __float2bfloat16(v - __bfloat162float(h));
}

DI void ldsm_x4(uint32_t* r, uint32_t addr) {
    asm volatile("ldmatrix.sync.aligned.m8n8.x4.shared.b16 {%0,%1,%2,%3}, [%4];"
                 : "=r"(r[0]), "=r"(r[1]), "=r"(r[2]), "=r"(r[3]) : "r"(addr));
}

DI void mma_bf16(float* c, const uint32_t* a, uint32_t b0, uint32_t b1) {
    asm volatile(
        "mma.sync.aligned.m16n8k16.row.col.f32.bf16.bf16.f32 "
        "{%0,%1,%2,%3}, {%4,%5,%6,%7}, {%8,%9}, {%0,%1,%2,%3};"
        : "+f"(c[0]), "+f"(c[1]), "+f"(c[2]), "+f"(c[3])
        : "r"(a[0]), "r"(a[1]), "r"(a[2]), "r"(a[3]), "r"(b0), "r"(b1));
}

DI void cp_async16(uint32_t saddr, const void* gptr) {
    asm volatile("cp.async.cg.shared.global [%0], [%1], 16;"
                 :: "r"(saddr), "l"(gptr));
}
DI void cp_commit() { asm volatile("cp.async.commit_group;" ::: "memory"); }
template <int N> DI void cp_wait() {
    asm volatile("cp.async.wait_group %0;" :: "n"(N) : "memory");
}

// ---------------------------------------------------------------------------
// One K-stage (32) of the split-bf16 warp-tile MMA: 2 k16 steps, warp 32x64.
// Product-major issue order (R8 best configuration).
// ---------------------------------------------------------------------------
DI void compute_stage(uint32_t base, int lane, int wm, int wn,
                      float acc[2][8][4]) {
    const uint32_t sAhi = base;
    const uint32_t sAlo = base + MAT_ELE * 2;
    const uint32_t sBhi = base + MAT_ELE * 4;
    const uint32_t sBlo = base + MAT_ELE * 6;
    const int lrow = lane & 15;
    const int lkh  = lane >> 4;
#pragma unroll
    for (int ks = 0; ks < 2; ++ks) {
        const uint32_t kbyte = (uint32_t)(ks * 16 + 8 * lkh) * 2;
        uint32_t ah[2][4], al[2][4];
#pragma unroll
        for (int mt = 0; mt < 2; ++mt) {
            uint32_t off = (uint32_t)((wm * 32 + mt * 16 + lrow) * (RS * 2)) + kbyte;
            ldsm_x4(ah[mt], sAhi + off);
            ldsm_x4(al[mt], sAlo + off);
        }
#pragma unroll
        for (int np = 0; np < 4; ++np) {
            uint32_t off = (uint32_t)((wn * 64 + np * 16 + lrow) * (RS * 2)) + kbyte;
            uint32_t bh[4], bl[4];
            ldsm_x4(bh, sBhi + off);
            ldsm_x4(bl, sBlo + off);
#pragma unroll
            for (int mt = 0; mt < 2; ++mt)
#pragma unroll
                for (int w = 0; w < 2; ++w)
                    mma_bf16(acc[mt][np * 2 + w], ah[mt], bh[w], bh[w + 2]);
#pragma unroll
            for (int mt = 0; mt < 2; ++mt)
#pragma unroll
                for (int w = 0; w < 2; ++w)
                    mma_bf16(acc[mt][np * 2 + w], al[mt], bh[w], bh[w + 2]);
#pragma unroll
            for (int mt = 0; mt < 2; ++mt)
#pragma unroll
                for (int w = 0; w < 2; ++w)
                    mma_bf16(acc[mt][np * 2 + w], ah[mt], bl[w], bl[w + 2]);
        }
    }
}

// ---------------------------------------------------------------------------
// cp.async one stage: 4 matrices x 128 rows x 64B, 8 chunks of 16B per thread
// ---------------------------------------------------------------------------
DI void stage_cp(uint32_t sbase,
                 const __nv_bfloat16* Ah, const __nv_bfloat16* Al,
                 const __nv_bfloat16* Bh, const __nv_bfloat16* Bl,
                 int ldA, int ldB, int m0, int n0, int k0, int tid) {
    const int q = tid & 3;
    const int r = tid >> 2;
#pragma unroll
    for (int i = 0; i < 8; ++i) {
        const int mat = i >> 1;
        const int row = (i & 1) * 64 + r;
        const __nv_bfloat16* p = (mat == 0) ? Ah : (mat == 1) ? Al
                               : (mat == 2) ? Bh : Bl;
        const int ld = (mat < 2) ? ldA : ldB;
        const int r0 = (mat < 2) ? m0 : n0;
        uint32_t sa = sbase + (uint32_t)(mat * (MAT_ELE * 2) + row * (RS * 2) + q * 16);
        cp_async16(sa, p + (size_t)(r0 + row) * ld + k0 + q * 8);
    }
}

// ---------------------------------------------------------------------------
// prep: split weights to bf16 hi/lo (+ transpose W_o, W_c to [n][k])
// ---------------------------------------------------------------------------
__global__ void prep_kernel(const float* __restrict__ wo, const float* __restrict__ wc,
                            const float* __restrict__ lw) {
    int i = blockIdx.x * 256 + threadIdx.x;   // 0 .. 512*1024-1
    int n = i >> 10;
    int k = i & 1023;

    __nv_bfloat16 h, l;
    split_bf16(lw[i], h, l);                  // lin_w is [512][1024] = [n][k]
    g_lin_hi[i] = h;
    g_lin_lo[i] = l;

    if (k < 512) {
        int src = k * 512 + n;                // B[n][k] = W[k][n]
        int dst = n * 512 + k;
        split_bf16(wo[src], h, l);
        g_wo_hi[dst] = h; g_wo_lo[dst] = l;
        split_bf16(wc[src], h, l);
        g_wc_hi[dst] = h; g_wc_lo[dst] = l;
    }
}

// ---------------------------------------------------------------------------
// inverse index maps
// ---------------------------------------------------------------------------
__global__ void inv_init_kernel() {
    int i = blockIdx.x * 256 + threadIdx.x;   // 0 .. NNODE-1
    g_inv_p[i] = -1;
    g_inv_k[i] = -1;
}
__global__ void inv_fill_kernel(const int* __restrict__ idxp,
                                const int* __restrict__ idxk) {
    int m = blockIdx.x * 256 + threadIdx.x;   // 0 .. MMUT-1
    g_inv_p[idxp[m]] = m;
    g_inv_k[idxk[m]] = m;
}

// ---------------------------------------------------------------------------
// split inputs: h_p, h_k fp32 -> bf16 hi/lo  (pure bandwidth pass)
// ---------------------------------------------------------------------------
__global__ void split_inputs_kernel(const float* __restrict__ hp,
                                    const float* __restrict__ hk) {
    const size_t idx = (size_t)blockIdx.x * 256 + threadIdx.x;   // float4 index
    const int z = blockIdx.y;
    const float* src = z ? hk : hp;
    __nv_bfloat16* dh = z ? g_hk_hi : g_hp_hi;
    __nv_bfloat16* dl = z ? g_hk_lo : g_hp_lo;

    float4 v = *reinterpret_cast<const float4*>(src + idx * 4);
    __nv_bfloat16 h0, l0, h1, l1, h2, l2, h3, l3;
    split_bf16(v.x, h0, l0);
    split_bf16(v.y, h1, l1);
    split_bf16(v.z, h2, l2);
    split_bf16(v.w, h3, l3);
    __nv_bfloat162 ph0; ph0.x = h0; ph0.y = h1;
    __nv_bfloat162 ph1; ph1.x = h2; ph1.y = h3;
    __nv_bfloat162 pl0; pl0.x = l0; pl0.y = l1;
    __nv_bfloat162 pl1; pl1.x = l2; pl1.y = l3;
    uint2 uh; uh.x = *reinterpret_cast<uint32_t*>(&ph0); uh.y = *reinterpret_cast<uint32_t*>(&ph1);
    uint2 ul; ul.x = *reinterpret_cast<uint32_t*>(&pl0); ul.y = *reinterpret_cast<uint32_t*>(&pl1);
    *reinterpret_cast<uint2*>(dh + idx * 4) = uh;
    *reinterpret_cast<uint2*>(dl + idx * 4) = ul;
}

// ---------------------------------------------------------------------------
// GEMM1 (one z half per launch): trans = h @ W.
// Fused epilogue: mutual rows -> tanh + split into g_gh/g_gl (skip d_out write,
// those rows are fully overwritten by gemm2's scatter); other rows -> d_out.
// grid (4 n-tiles, 512 m-tiles), block 256, 2 CTAs/SM
// ---------------------------------------------------------------------------
__global__ __launch_bounds__(256, 2) void gemm1_kernel(float* __restrict__ out,
                                                       int z) {
    extern __shared__ __align__(16) __nv_bfloat16 sm[];
    const int tid = threadIdx.x, lane = tid & 31, wid = tid >> 5;
    const int wm = wid & 3, wn = wid >> 2;
    const int n0 = blockIdx.x * 128, m0 = blockIdx.y * 128;

    const __nv_bfloat16* Ah = z ? g_hk_hi : g_hp_hi;
    const __nv_bfloat16* Al = z ? g_hk_lo : g_hp_lo;
    const __nv_bfloat16* Bh = z ? g_wc_hi : g_wo_hi;
    const __nv_bfloat16* Bl = z ? g_wc_lo : g_wo_lo;
    const int* inv = z ? g_inv_k : g_inv_p;
    float* dst = out + (size_t)z * NNODE * DIM;
    const int coff = z ? DIM : 0;          // column offset into g (concat)

    float acc[2][8][4];
#pragma unroll
    for (int i = 0; i < 2; ++i)
#pragma unroll
        for (int j = 0; j < 8; ++j)
#pragma unroll
            for (int k = 0; k < 4; ++k) acc[i][j][k] = 0.f;

    const uint32_t sb = smem_u32(sm);

    stage_cp(sb, Ah, Al, Bh, Bl, DIM, DIM, m0, n0, 0, tid);
    cp_commit();

    const int S = DIM / 32;   // 16 stages
#pragma unroll 1
    for (int s = 0; s < S; ++s) {
        if (s + 1 < S) {
            stage_cp(sb + ((s + 1) & 1) * BUF_BYTES, Ah, Al, Bh, Bl,
                     DIM, DIM, m0, n0, (s + 1) * 32, tid);
            cp_commit();
            cp_wait<1>();
        } else {
            cp_wait<0>();
        }
        __syncthreads();
        compute_stage(sb + (s & 1) * BUF_BYTES, lane, wm, wn, acc);
        __syncthreads();
    }

    // Epilogue: per accumulator row, route to g (mutual) or d_out (plain)
#pragma unroll
    for (int mt = 0; mt < 2; ++mt) {
#pragma unroll
        for (int r = 0; r < 2; ++r) {
            const int row = m0 + wm * 32 + mt * 16 + (lane >> 2) + r * 8;
            const int m = inv[row];
            if (m >= 0) {
                __nv_bfloat16* gh = g_gh + (size_t)m * (2 * DIM) + coff;
                __nv_bfloat16* gl = g_gl + (size_t)m * (2 * DIM) + coff;
#pragma unroll
                for (int nt = 0; nt < 8; ++nt) {
                    int gcol = n0 + wn * 64 + nt * 8 + (lane & 3) * 2;
                    float t0 = tanhf(acc[mt][nt][r * 2 + 0]);
                    float t1 = tanhf(acc[mt][nt][r * 2 + 1]);
                    __nv_bfloat16 h0, l0, h1, l1;
                    split_bf16(t0, h0, l0);
                    split_bf16(t1, h1, l1);
                    __nv_bfloat162 ph; ph.x = h0; ph.y = h1;
                    __nv_bfloat162 pl; pl.x = l0; pl.y = l1;
                    *reinterpret_cast<__nv_bfloat162*>(gh + gcol) = ph;
                    *reinterpret_cast<__nv_bfloat162*>(gl + gcol) = pl;
                }
            } else {
                float* rp = dst + (size_t)row * DIM;
#pragma unroll
                for (int nt = 0; nt < 8; ++nt) {
                    int gcol = n0 + wn * 64 + nt * 8 + (lane & 3) * 2;
                    float2 v;
                    v.x = acc[mt][nt][r * 2 + 0];
                    v.y = acc[mt][nt][r * 2 + 1];
                    *reinterpret_cast<float2*>(rp + gcol) = v;
                }
            }
        }
    }
}

// ---------------------------------------------------------------------------
// GEMM2: rows = leaky_relu(g @ lin_w^T + lin_b) + bias, scattered into both
//        halves of d_out.  grid (4 n-tiles, 256 m-tiles), block 256, 2 CTAs/SM
// ---------------------------------------------------------------------------
__global__ __launch_bounds__(256, 2) void gemm2_kernel(
    const int* __restrict__ idxp, const int* __restrict__ idxk,
    const float* __restrict__ lin_b, const float* __restrict__ bias,
    float* __restrict__ out) {
    extern __shared__ __align__(16) __nv_bfloat16 sm[];
    const int tid = threadIdx.x, lane = tid & 31, wid = tid >> 5;
    const int wm = wid & 3, wn = wid >> 2;
    const int n0 = blockIdx.x * 128, m0 = blockIdx.y * 128;

    float* outp = out;
    float* outk = out + (size_t)NNODE * DIM;

    float acc[2][8][4];
#pragma unroll
    for (int i = 0; i < 2; ++i)
#pragma unroll
        for (int j = 0; j < 8; ++j)
#pragma unroll
            for (int k = 0; k < 4; ++k) acc[i][j][k] = 0.f;

    const uint32_t sb = smem_u32(sm);

    stage_cp(sb, g_gh, g_gl, g_lin_hi, g_lin_lo, 2 * DIM, 2 * DIM, m0, n0, 0, tid);
    cp_commit();

    const int S = (2 * DIM) / 32;   // 32 stages
#pragma unroll 1
    for (int s = 0; s < S; ++s) {
        if (s + 1 < S) {
            stage_cp(sb + ((s + 1) & 1) * BUF_BYTES, g_gh, g_gl, g_lin_hi, g_lin_lo,
                     2 * DIM, 2 * DIM, m0, n0, (s + 1) * 32, tid);
            cp_commit();
            cp_wait<1>();
        } else {
            cp_wait<0>();
        }
        __syncthreads();
        compute_stage(sb + (s & 1) * BUF_BYTES, lane, wm, wn, acc);
        __syncthreads();
    }

#pragma unroll
    for (int mt = 0; mt < 2; ++mt) {
        int grow = m0 + wm * 32 + mt * 16 + (lane >> 2);
        int p0 = idxp[grow], p1 = idxp[grow + 8];
        int q0 = idxk[grow], q1 = idxk[grow + 8];
#pragma unroll
        for (int nt = 0; nt < 8; ++nt) {
            int gcol = n0 + wn * 64 + nt * 8 + (lane & 3) * 2;
            float2 lb = *reinterpret_cast<const float2*>(lin_b + gcol);
            float2 bs = *reinterpret_cast<const float2*>(bias + gcol);
            float x0 = acc[mt][nt][0] + lb.x;
            float x1 = acc[mt][nt][1] + lb.y;
            float x2 = acc[mt][nt][2] + lb.x;
            float x3 = acc[mt][nt][3] + lb.y;
            x0 = (x0 >= 0.f ? x0 : 0.01f * x0) + bs.x;
            x1 = (x1 >= 0.f ? x1 : 0.01f * x1) + bs.y;
            x2 = (x2 >= 0.f ? x2 : 0.01f * x2) + bs.x;
            x3 = (x3 >= 0.f ? x3 : 0.01f * x3) + bs.y;
            float2 v0; v0.x = x0; v0.y = x1;
            float2 v1; v1.x = x2; v1.y = x3;
            *reinterpret_cast<float2*>(outp + (size_t)p0 * DIM + gcol) = v0;
            *reinterpret_cast<float2*>(outp + (size_t)p1 * DIM + gcol) = v1;
            *reinterpret_cast<float2*>(outk + (size_t)q0 * DIM + gcol) = v0;
            *reinterpret_cast<float2*>(outk + (size_t)q1 * DIM + gcol) = v1;
        }
    }
}

// ---------------------------------------------------------------------------
// Launch
// ---------------------------------------------------------------------------
extern "C" void kernel_launch(void* const* d_in, const int* in_sizes, int n_in,
                              void* d_out, int out_size) {
    const float* h_p  = (const float*)d_in[0];
    const float* h_k  = (const float*)d_in[1];
    const int*   idxp = (const int*)d_in[2];
    const int*   idxk = (const int*)d_in[3];
    // d_in[4] = last_x (unused by the reference computation)
    const float* wo   = (const float*)d_in[5];
    const float* wc   = (const float*)d_in[6];
    const float* lw   = (const float*)d_in[7];
    const float* lb   = (const float*)d_in[8];
    const float* bias = (const float*)d_in[9];
    float* out = (float*)d_out;

    cudaFuncSetAttribute(gemm1_kernel, cudaFuncAttributeMaxDynamicSharedMemorySize, SMEM_BYTES);
    cudaFuncSetAttribute(gemm2_kernel, cudaFuncAttributeMaxDynamicSharedMemorySize, SMEM_BYTES);

    prep_kernel<<<(512 * 1024) / 256, 256>>>(wo, wc, lw);

    inv_init_kernel<<<NNODE / 256, 256>>>();
    inv_fill_kernel<<<MMUT / 256, 256>>>(idxp, idxk);

    split_inputs_kernel<<<dim3((NNODE * DIM / 4) / 256, 2), 256>>>(h_p, h_k);

    gemm1_kernel<<<dim3(DIM / 128, NNODE / 128), 256, SMEM_BYTES>>>(out, 0);
    gemm1_kernel<<<dim3(DIM / 128, NNODE / 128), 256, SMEM_BYTES>>>(out, 1);

    gemm2_kernel<<<dim3(DIM / 128, MMUT / 128), 256, SMEM_BYTES>>>(idxp, idxk, lb, bias, out);
}

// round 12
// speedup vs baseline: 1.2857x; 1.2498x over previous
#include <cuda_runtime.h>
#include <cuda_bf16.h>
#include <cuda_fp16.h>
#include <cstdint>

// ---------------------------------------------------------------------------
// Problem constants
// ---------------------------------------------------------------------------
#define DIM   512
#define NNODE 65536
#define MMUT  32768

// ---------------------------------------------------------------------------
// Smem tile geometry: CTA tile 128x128, K-stage 32, rows padded to 40 halves
// ---------------------------------------------------------------------------
#define RS      40                    // row stride in 2B elems (80 bytes)
#define MAT_ELE (128 * RS)            // one 128x32(+pad) matrix = 5120 elems
// GEMM2 (4 matrices) buffer
#define BUF_ELE4 (4 * MAT_ELE)
#define BUF_BYTES4 (BUF_ELE4 * 2)     // 40960
#define SMEM_BYTES4 (2 * BUF_BYTES4)  // 81920
// GEMM1 (3 matrices: A_hi, B_hi, B_lo) buffer
#define BUF_BYTES3 (3 * MAT_ELE * 2)  // 30720
#define SMEM_BYTES3 (2 * BUF_BYTES3)  // 61440

#define DI __device__ __forceinline__

// ---------------------------------------------------------------------------
// Device scratch (__device__ globals only — no allocations)
// ---------------------------------------------------------------------------
// GEMM1 weights: fp16 hi/lo, transposed to [n][k]
__device__ __half g_wo_hi[DIM * DIM];
__device__ __half g_wo_lo[DIM * DIM];
__device__ __half g_wc_hi[DIM * DIM];
__device__ __half g_wc_lo[DIM * DIM];
// GEMM2 weights: bf16 hi/lo (3-product path)
__device__ __nv_bfloat16 g_lin_hi[DIM * 2 * DIM];
__device__ __nv_bfloat16 g_lin_lo[DIM * 2 * DIM];
// inputs: h_p, h_k as fp16 (hi only — 2-product scheme)
__device__ __half g_hp[(size_t)NNODE * DIM];
__device__ __half g_hk[(size_t)NNODE * DIM];
// gathered + tanh'd + split GEMM2 A matrix: [MMUT, 1024] bf16 hi/lo
__device__ __nv_bfloat16 g_gh[(size_t)MMUT * 2 * DIM];
__device__ __nv_bfloat16 g_gl[(size_t)MMUT * 2 * DIM];
// inverse index maps: node -> mutual position (or -1)
__device__ int g_inv_p[NNODE];
__device__ int g_inv_k[NNODE];

// ---------------------------------------------------------------------------
// Helpers
// ---------------------------------------------------------------------------
DI uint32_t smem_u32(const void* p) {
    uint32_t a;
    asm("{ .reg .u64 t; cvta.to.shared.u64 t, %1; cvt.u32.u64 %0, t; }"
        : "=r"(a) : "l"(p));
    return a;
}

DI void split_bf16(float v, __nv_bfloat16& h, __nv_bfloat16& l) {
    h = __float2bfloat16(v);
    l = __float2bfloat16(v - __bfloat162float(h));
}
DI void split_f16(float v, __half& h, __half& l) {
    h = __float2half_rn(v);
    l = __float2half_rn(v - __half2float(h));
}

DI void ldsm_x4(uint32_t* r, uint32_t addr) {
    asm volatile("ldmatrix.sync.aligned.m8n8.x4.shared.b16 {%0,%1,%2,%3}, [%4];"
                 : "=r"(r[0]), "=r"(r[1]), "=r"(r[2]), "=r"(r[3]) : "r"(addr));
}

DI void mma_bf16(float* c, const uint32_t* a, uint32_t b0, uint32_t b1) {
    asm volatile(
        "mma.sync.aligned.m16n8k16.row.col.f32.bf16.bf16.f32 "
        "{%0,%1,%2,%3}, {%4,%5,%6,%7}, {%8,%9}, {%0,%1,%2,%3};"
        : "+f"(c[0]), "+f"(c[1]), "+f"(c[2]), "+f"(c[3])
        : "r"(a[0]), "r"(a[1]), "r"(a[2]), "r"(a[3]), "r"(b0), "r"(b1));
}
DI void mma_f16(float* c, const uint32_t* a, uint32_t b0, uint32_t b1) {
    asm volatile(
        "mma.sync.aligned.m16n8k16.row.col.f32.f16.f16.f32 "
        "{%0,%1,%2,%3}, {%4,%5,%6,%7}, {%8,%9}, {%0,%1,%2,%3};"
        : "+f"(c[0]), "+f"(c[1]), "+f"(c[2]), "+f"(c[3])
        : "r"(a[0]), "r"(a[1]), "r"(a[2]), "r"(a[3]), "r"(b0), "r"(b1));
}

DI void cp_async16(uint32_t saddr, const void* gptr) {
    asm volatile("cp.async.cg.shared.global [%0], [%1], 16;"
                 :: "r"(saddr), "l"(gptr));
}
DI void cp_commit() { asm volatile("cp.async.commit_group;" ::: "memory"); }
template <int N> DI void cp_wait() {
    asm volatile("cp.async.wait_group %0;" :: "n"(N) : "memory");
}

// ---------------------------------------------------------------------------
// GEMM1 K-stage (32): fp16 2-product, warp tile 32x64.
// C = A_hi*B_hi + A_hi*B_lo  (dropped A_lo*B ~ 2^-12 relative)
// ---------------------------------------------------------------------------
DI void compute_stage_g1(uint32_t base, int lane, int wm, int wn,
                         float acc[2][8][4]) {
    const uint32_t sA  = base;
    const uint32_t sBh = base + MAT_ELE * 2;
    const uint32_t sBl = base + MAT_ELE * 4;
    const int lrow = lane & 15;
    const int lkh  = lane >> 4;
#pragma unroll
    for (int ks = 0; ks < 2; ++ks) {
        const uint32_t kbyte = (uint32_t)(ks * 16 + 8 * lkh) * 2;
        uint32_t ah[2][4];
#pragma unroll
        for (int mt = 0; mt < 2; ++mt) {
            uint32_t off = (uint32_t)((wm * 32 + mt * 16 + lrow) * (RS * 2)) + kbyte;
            ldsm_x4(ah[mt], sA + off);
        }
#pragma unroll
        for (int np = 0; np < 4; ++np) {
            uint32_t off = (uint32_t)((wn * 64 + np * 16 + lrow) * (RS * 2)) + kbyte;
            uint32_t bh[4], bl[4];
            ldsm_x4(bh, sBh + off);
            ldsm_x4(bl, sBl + off);
#pragma unroll
            for (int mt = 0; mt < 2; ++mt)
#pragma unroll
                for (int w = 0; w < 2; ++w)
                    mma_f16(acc[mt][np * 2 + w], ah[mt], bh[w], bh[w + 2]);
#pragma unroll
            for (int mt = 0; mt < 2; ++mt)
#pragma unroll
                for (int w = 0; w < 2; ++w)
                    mma_f16(acc[mt][np * 2 + w], ah[mt], bl[w], bl[w + 2]);
        }
    }
}

// ---------------------------------------------------------------------------
// GEMM2 K-stage (32): bf16 3-product, warp tile 32x64 (unchanged R8 path)
// ---------------------------------------------------------------------------
DI void compute_stage_g2(uint32_t base, int lane, int wm, int wn,
                         float acc[2][8][4]) {
    const uint32_t sAhi = base;
    const uint32_t sAlo = base + MAT_ELE * 2;
    const uint32_t sBhi = base + MAT_ELE * 4;
    const uint32_t sBlo = base + MAT_ELE * 6;
    const int lrow = lane & 15;
    const int lkh  = lane >> 4;
#pragma unroll
    for (int ks = 0; ks < 2; ++ks) {
        const uint32_t kbyte = (uint32_t)(ks * 16 + 8 * lkh) * 2;
        uint32_t ah[2][4], al[2][4];
#pragma unroll
        for (int mt = 0; mt < 2; ++mt) {
            uint32_t off = (uint32_t)((wm * 32 + mt * 16 + lrow) * (RS * 2)) + kbyte;
            ldsm_x4(ah[mt], sAhi + off);
            ldsm_x4(al[mt], sAlo + off);
        }
#pragma unroll
        for (int np = 0; np < 4; ++np) {
            uint32_t off = (uint32_t)((wn * 64 + np * 16 + lrow) * (RS * 2)) + kbyte;
            uint32_t bh[4], bl[4];
            ldsm_x4(bh, sBhi + off);
            ldsm_x4(bl, sBlo + off);
#pragma unroll
            for (int mt = 0; mt < 2; ++mt)
#pragma unroll
                for (int w = 0; w < 2; ++w)
                    mma_bf16(acc[mt][np * 2 + w], ah[mt], bh[w], bh[w + 2]);
#pragma unroll
            for (int mt = 0; mt < 2; ++mt)
#pragma unroll
                for (int w = 0; w < 2; ++w)
                    mma_bf16(acc[mt][np * 2 + w], al[mt], bh[w], bh[w + 2]);
#pragma unroll
            for (int mt = 0; mt < 2; ++mt)
#pragma unroll
                for (int w = 0; w < 2; ++w)
                    mma_bf16(acc[mt][np * 2 + w], ah[mt], bl[w], bl[w + 2]);
        }
    }
}

// ---------------------------------------------------------------------------
// cp.async stage loaders
// ---------------------------------------------------------------------------
// GEMM1: 3 matrices (A, B_hi, B_lo), 6 chunks of 16B per thread (256 threads)
DI void stage_cp_g1(uint32_t sbase, const __half* A,
                    const __half* Bh, const __half* Bl,
                    int m0, int n0, int k0, int tid) {
    const int q = tid & 3;
    const int r = tid >> 2;
#pragma unroll
    for (int i = 0; i < 6; ++i) {
        const int mat = i >> 1;
        const int row = (i & 1) * 64 + r;
        const __half* p = (mat == 0) ? A : (mat == 1) ? Bh : Bl;
        const int r0 = (mat == 0) ? m0 : n0;
        uint32_t sa = sbase + (uint32_t)(mat * (MAT_ELE * 2) + row * (RS * 2) + q * 16);
        cp_async16(sa, p + (size_t)(r0 + row) * DIM + k0 + q * 8);
    }
}
// GEMM2: 4 matrices, 8 chunks of 16B per thread
DI void stage_cp_g2(uint32_t sbase,
                    const __nv_bfloat16* Ah, const __nv_bfloat16* Al,
                    const __nv_bfloat16* Bh, const __nv_bfloat16* Bl,
                    int m0, int n0, int k0, int tid) {
    const int q = tid & 3;
    const int r = tid >> 2;
#pragma unroll
    for (int i = 0; i < 8; ++i) {
        const int mat = i >> 1;
        const int row = (i & 1) * 64 + r;
        const __nv_bfloat16* p = (mat == 0) ? Ah : (mat == 1) ? Al
                               : (mat == 2) ? Bh : Bl;
        const int r0 = (mat < 2) ? m0 : n0;
        uint32_t sa = sbase + (uint32_t)(mat * (MAT_ELE * 2) + row * (RS * 2) + q * 16);
        cp_async16(sa, p + (size_t)(r0 + row) * (2 * DIM) + k0 + q * 8);
    }
}

// ---------------------------------------------------------------------------
// prep: weights (wo/wc -> fp16 hi/lo transposed; lin -> bf16 hi/lo) + inv init
// ---------------------------------------------------------------------------
__global__ void prep_kernel(const float* __restrict__ wo, const float* __restrict__ wc,
                            const float* __restrict__ lw) {
    int i = blockIdx.x * 256 + threadIdx.x;   // 0 .. 512*1024-1
    int n = i >> 10;
    int k = i & 1023;

    __nv_bfloat16 bh, blo;
    split_bf16(lw[i], bh, blo);               // lin_w is [512][1024] = [n][k]
    g_lin_hi[i] = bh;
    g_lin_lo[i] = blo;

    if (k < 512) {
        int src = k * 512 + n;                // B[n][k] = W[k][n]
        int dst = n * 512 + k;
        __half h, l;
        split_f16(wo[src], h, l);
        g_wo_hi[dst] = h; g_wo_lo[dst] = l;
        split_f16(wc[src], h, l);
        g_wc_hi[dst] = h; g_wc_lo[dst] = l;
    }
    if (i < NNODE) { g_inv_p[i] = -1; g_inv_k[i] = -1; }
}

__global__ void inv_fill_kernel(const int* __restrict__ idxp,
                                const int* __restrict__ idxk) {
    int m = blockIdx.x * 256 + threadIdx.x;   // 0 .. MMUT-1
    g_inv_p[idxp[m]] = m;
    g_inv_k[idxk[m]] = m;
}

// ---------------------------------------------------------------------------
// split inputs: h_p, h_k fp32 -> fp16 (hi only)
// ---------------------------------------------------------------------------
__global__ void split_inputs_kernel(const float* __restrict__ hp,
                                    const float* __restrict__ hk) {
    const size_t idx = (size_t)blockIdx.x * 256 + threadIdx.x;   // float4 index
    const int z = blockIdx.y;
    const float* src = z ? hk : hp;
    __half* dh = z ? g_hk : g_hp;

    float4 v = *reinterpret_cast<const float4*>(src + idx * 4);
    __half2 a; a.x = __float2half_rn(v.x); a.y = __float2half_rn(v.y);
    __half2 b; b.x = __float2half_rn(v.z); b.y = __float2half_rn(v.w);
    uint2 u;
    u.x = *reinterpret_cast<uint32_t*>(&a);
    u.y = *reinterpret_cast<uint32_t*>(&b);
    *reinterpret_cast<uint2*>(dh + idx * 4) = u;
}

// ---------------------------------------------------------------------------
// GEMM1 (one z half per launch): trans = h @ W  (fp16 2-product).
// Fused epilogue: mutual rows -> tanh + bf16 split into g_gh/g_gl;
// other rows -> d_out.
// grid (4 n-tiles, 512 m-tiles), block 256, 2 CTAs/SM
// ---------------------------------------------------------------------------
__global__ __launch_bounds__(256, 2) void gemm1_kernel(float* __restrict__ out,
                                                       int z) {
    extern __shared__ __align__(16) __half sm1[];
    const int tid = threadIdx.x, lane = tid & 31, wid = tid >> 5;
    const int wm = wid & 3, wn = wid >> 2;
    const int n0 = blockIdx.x * 128, m0 = blockIdx.y * 128;

    const __half* A  = z ? g_hk : g_hp;
    const __half* Bh = z ? g_wc_hi : g_wo_hi;
    const __half* Bl = z ? g_wc_lo : g_wo_lo;
    const int* inv = z ? g_inv_k : g_inv_p;
    float* dst = out + (size_t)z * NNODE * DIM;
    const int coff = z ? DIM : 0;          // column offset into g (concat)

    float acc[2][8][4];
#pragma unroll
    for (int i = 0; i < 2; ++i)
#pragma unroll
        for (int j = 0; j < 8; ++j)
#pragma unroll
            for (int k = 0; k < 4; ++k) acc[i][j][k] = 0.f;

    const uint32_t sb = smem_u32(sm1);

    stage_cp_g1(sb, A, Bh, Bl, m0, n0, 0, tid);
    cp_commit();

    const int S = DIM / 32;   // 16 stages
#pragma unroll 1
    for (int s = 0; s < S; ++s) {
        if (s + 1 < S) {
            stage_cp_g1(sb + ((s + 1) & 1) * BUF_BYTES3, A, Bh, Bl,
                        m0, n0, (s + 1) * 32, tid);
            cp_commit();
            cp_wait<1>();
        } else {
            cp_wait<0>();
        }
        __syncthreads();
        compute_stage_g1(sb + (s & 1) * BUF_BYTES3, lane, wm, wn, acc);
        __syncthreads();
    }

    // Epilogue: per accumulator row, route to g (mutual) or d_out (plain)
#pragma unroll
    for (int mt = 0; mt < 2; ++mt) {
#pragma unroll
        for (int r = 0; r < 2; ++r) {
            const int row = m0 + wm * 32 + mt * 16 + (lane >> 2) + r * 8;
            const int m = inv[row];
            if (m >= 0) {
                __nv_bfloat16* gh = g_gh + (size_t)m * (2 * DIM) + coff;
                __nv_bfloat16* gl = g_gl + (size_t)m * (2 * DIM) + coff;
#pragma unroll
                for (int nt = 0; nt < 8; ++nt) {
                    int gcol = n0 + wn * 64 + nt * 8 + (lane & 3) * 2;
                    float t0 = tanhf(acc[mt][nt][r * 2 + 0]);
                    float t1 = tanhf(acc[mt][nt][r * 2 + 1]);
                    __nv_bfloat16 h0, l0, h1, l1;
                    split_bf16(t0, h0, l0);
                    split_bf16(t1, h1, l1);
                    __nv_bfloat162 ph; ph.x = h0; ph.y = h1;
                    __nv_bfloat162 pl; pl.x = l0; pl.y = l1;
                    *reinterpret_cast<__nv_bfloat162*>(gh + gcol) = ph;
                    *reinterpret_cast<__nv_bfloat162*>(gl + gcol) = pl;
                }
            } else {
                float* rp = dst + (size_t)row * DIM;
#pragma unroll
                for (int nt = 0; nt < 8; ++nt) {
                    int gcol = n0 + wn * 64 + nt * 8 + (lane & 3) * 2;
                    float2 v;
                    v.x = acc[mt][nt][r * 2 + 0];
                    v.y = acc[mt][nt][r * 2 + 1];
                    *reinterpret_cast<float2*>(rp + gcol) = v;
                }
            }
        }
    }
}

// ---------------------------------------------------------------------------
// GEMM2: rows = leaky_relu(g @ lin_w^T + lin_b) + bias, scattered into both
//        halves of d_out.  grid (4 n-tiles, 256 m-tiles), block 256, 2 CTAs/SM
// ---------------------------------------------------------------------------
__global__ __launch_bounds__(256, 2) void gemm2_kernel(
    const int* __restrict__ idxp, const int* __restrict__ idxk,
    const float* __restrict__ lin_b, const float* __restrict__ bias,
    float* __restrict__ out) {
    extern __shared__ __align__(16) __nv_bfloat16 sm2[];
    const int tid = threadIdx.x, lane = tid & 31, wid = tid >> 5;
    const int wm = wid & 3, wn = wid >> 2;
    const int n0 = blockIdx.x * 128, m0 = blockIdx.y * 128;

    float* outp = out;
    float* outk = out + (size_t)NNODE * DIM;

    float acc[2][8][4];
#pragma unroll
    for (int i = 0; i < 2; ++i)
#pragma unroll
        for (int j = 0; j < 8; ++j)
#pragma unroll
            for (int k = 0; k < 4; ++k) acc[i][j][k] = 0.f;

    const uint32_t sb = smem_u32(sm2);

    stage_cp_g2(sb, g_gh, g_gl, g_lin_hi, g_lin_lo, m0, n0, 0, tid);
    cp_commit();

    const int S = (2 * DIM) / 32;   // 32 stages
#pragma unroll 1
    for (int s = 0; s < S; ++s) {
        if (s + 1 < S) {
            stage_cp_g2(sb + ((s + 1) & 1) * BUF_BYTES4, g_gh, g_gl,
                        g_lin_hi, g_lin_lo, m0, n0, (s + 1) * 32, tid);
            cp_commit();
            cp_wait<1>();
        } else {
            cp_wait<0>();
        }
        __syncthreads();
        compute_stage_g2(sb + (s & 1) * BUF_BYTES4, lane, wm, wn, acc);
        __syncthreads();
    }

#pragma unroll
    for (int mt = 0; mt < 2; ++mt) {
        int grow = m0 + wm * 32 + mt * 16 + (lane >> 2);
        int p0 = idxp[grow], p1 = idxp[grow + 8];
        int q0 = idxk[grow], q1 = idxk[grow + 8];
#pragma unroll
        for (int nt = 0; nt < 8; ++nt) {
            int gcol = n0 + wn * 64 + nt * 8 + (lane & 3) * 2;
            float2 lb = *reinterpret_cast<const float2*>(lin_b + gcol);
            float2 bs = *reinterpret_cast<const float2*>(bias + gcol);
            float x0 = acc[mt][nt][0] + lb.x;
            float x1 = acc[mt][nt][1] + lb.y;
            float x2 = acc[mt][nt][2] + lb.x;
            float x3 = acc[mt][nt][3] + lb.y;
            x0 = (x0 >= 0.f ? x0 : 0.01f * x0) + bs.x;
            x1 = (x1 >= 0.f ? x1 : 0.01f * x1) + bs.y;
            x2 = (x2 >= 0.f ? x2 : 0.01f * x2) + bs.x;
            x3 = (x3 >= 0.f ? x3 : 0.01f * x3) + bs.y;
            float2 v0; v0.x = x0; v0.y = x1;
            float2 v1; v1.x = x2; v1.y = x3;
            *reinterpret_cast<float2*>(outp + (size_t)p0 * DIM + gcol) = v0;
            *reinterpret_cast<float2*>(outp + (size_t)p1 * DIM + gcol) = v1;
            *reinterpret_cast<float2*>(outk + (size_t)q0 * DIM + gcol) = v0;
            *reinterpret_cast<float2*>(outk + (size_t)q1 * DIM + gcol) = v1;
        }
    }
}

// ---------------------------------------------------------------------------
// Launch
// ---------------------------------------------------------------------------
extern "C" void kernel_launch(void* const* d_in, const int* in_sizes, int n_in,
                              void* d_out, int out_size) {
    const float* h_p  = (const float*)d_in[0];
    const float* h_k  = (const float*)d_in[1];
    const int*   idxp = (const int*)d_in[2];
    const int*   idxk = (const int*)d_in[3];
    // d_in[4] = last_x (unused by the reference computation)
    const float* wo   = (const float*)d_in[5];
    const float* wc   = (const float*)d_in[6];
    const float* lw   = (const float*)d_in[7];
    const float* lb   = (const float*)d_in[8];
    const float* bias = (const float*)d_in[9];
    float* out = (float*)d_out;

    cudaFuncSetAttribute(gemm1_kernel, cudaFuncAttributeMaxDynamicSharedMemorySize, SMEM_BYTES3);
    cudaFuncSetAttribute(gemm2_kernel, cudaFuncAttributeMaxDynamicSharedMemorySize, SMEM_BYTES4);

    prep_kernel<<<(512 * 1024) / 256, 256>>>(wo, wc, lw);

    inv_fill_kernel<<<MMUT / 256, 256>>>(idxp, idxk);

    split_inputs_kernel<<<dim3((NNODE * DIM / 4) / 256, 2), 256>>>(h_p, h_k);

    gemm1_kernel<<<dim3(DIM / 128, NNODE / 128), 256, SMEM_BYTES3>>>(out, 0);
    gemm1_kernel<<<dim3(DIM / 128, NNODE / 128), 256, SMEM_BYTES3>>>(out, 1);

    gemm2_kernel<<<dim3(DIM / 128, MMUT / 128), 256, SMEM_BYTES4>>>(idxp, idxk, lb, bias, out);
}

// round 13
// speedup vs baseline: 1.4874x; 1.1568x over previous
#include <cuda_runtime.h>
#include <cuda_bf16.h>
#include <cuda_fp16.h>
#include <cstdint>

// ---------------------------------------------------------------------------
// Problem constants
// ---------------------------------------------------------------------------
#define DIM   512
#define NNODE 65536
#define MMUT  32768

// ---------------------------------------------------------------------------
// Smem tile geometry: CTA tile 128x128, K-stage 32, rows padded to 40 halves
// 3 matrices per stage (A, B_hi, B_lo), 3-stage ring buffer
// ---------------------------------------------------------------------------
#define RS      40                    // row stride in 2B elems (80 bytes)
#define MAT_ELE (128 * RS)            // one 128x32(+pad) matrix = 5120 elems
#define BUF_BYTES (3 * MAT_ELE * 2)   // 30720 per stage
#define SMEM_BYTES (3 * BUF_BYTES)    // 92160 (3-stage ring)

#define DI __device__ __forceinline__

// ---------------------------------------------------------------------------
// Device scratch (__device__ globals only — no allocations)
// ---------------------------------------------------------------------------
// GEMM1 weights: fp16 hi/lo, transposed to [n][k]
__device__ __half g_wo_hi[DIM * DIM];
__device__ __half g_wo_lo[DIM * DIM];
__device__ __half g_wc_hi[DIM * DIM];
__device__ __half g_wc_lo[DIM * DIM];
// GEMM2 weights: fp16 hi/lo, [n=512][k=1024]
__device__ __half g_lin_hi[DIM * 2 * DIM];
__device__ __half g_lin_lo[DIM * 2 * DIM];
// inputs: h_p, h_k as fp16 (hi only — 2-product scheme)
__device__ __half g_hp[(size_t)NNODE * DIM];
__device__ __half g_hk[(size_t)NNODE * DIM];
// gathered + tanh'd GEMM2 A matrix: [MMUT, 1024] fp16 (hi only)
__device__ __half g_g[(size_t)MMUT * 2 * DIM];
// inverse index maps: node -> mutual position (or -1)
__device__ int g_inv_p[NNODE];
__device__ int g_inv_k[NNODE];

// ---------------------------------------------------------------------------
// Helpers
// ---------------------------------------------------------------------------
DI uint32_t smem_u32(const void* p) {
    uint32_t a;
    asm("{ .reg .u64 t; cvta.to.shared.u64 t, %1; cvt.u32.u64 %0, t; }"
        : "=r"(a) : "l"(p));
    return a;
}

DI void split_f16(float v, __half& h, __half& l) {
    h = __float2half_rn(v);
    l = __float2half_rn(v - __half2float(h));
}

DI void ldsm_x4(uint32_t* r, uint32_t addr) {
    asm volatile("ldmatrix.sync.aligned.m8n8.x4.shared.b16 {%0,%1,%2,%3}, [%4];"
                 : "=r"(r[0]), "=r"(r[1]), "=r"(r[2]), "=r"(r[3]) : "r"(addr));
}

DI void mma_f16(float* c, const uint32_t* a, uint32_t b0, uint32_t b1) {
    asm volatile(
        "mma.sync.aligned.m16n8k16.row.col.f32.f16.f16.f32 "
        "{%0,%1,%2,%3}, {%4,%5,%6,%7}, {%8,%9}, {%0,%1,%2,%3};"
        : "+f"(c[0]), "+f"(c[1]), "+f"(c[2]), "+f"(c[3])
        : "r"(a[0]), "r"(a[1]), "r"(a[2]), "r"(a[3]), "r"(b0), "r"(b1));
}

DI void cp_async16(uint32_t saddr, const void* gptr) {
    asm volatile("cp.async.cg.shared.global [%0], [%1], 16;"
                 :: "r"(saddr), "l"(gptr));
}
DI void cp_commit() { asm volatile("cp.async.commit_group;" ::: "memory"); }
template <int N> DI void cp_wait() {
    asm volatile("cp.async.wait_group %0;" :: "n"(N) : "memory");
}

// ---------------------------------------------------------------------------
// One K-stage (32): fp16 2-product, warp tile 32x64.
// C = A_hi*B_hi + A_hi*B_lo  (dropped A_lo*B ~ 2^-12 relative)
// ---------------------------------------------------------------------------
DI void compute_stage(uint32_t base, int lane, int wm, int wn,
                      float acc[2][8][4]) {
    const uint32_t sA  = base;
    const uint32_t sBh = base + MAT_ELE * 2;
    const uint32_t sBl = base + MAT_ELE * 4;
    const int lrow = lane & 15;
    const int lkh  = lane >> 4;
#pragma unroll
    for (int ks = 0; ks < 2; ++ks) {
        const uint32_t kbyte = (uint32_t)(ks * 16 + 8 * lkh) * 2;
        uint32_t ah[2][4];
#pragma unroll
        for (int mt = 0; mt < 2; ++mt) {
            uint32_t off = (uint32_t)((wm * 32 + mt * 16 + lrow) * (RS * 2)) + kbyte;
            ldsm_x4(ah[mt], sA + off);
        }
#pragma unroll
        for (int np = 0; np < 4; ++np) {
            uint32_t off = (uint32_t)((wn * 64 + np * 16 + lrow) * (RS * 2)) + kbyte;
            uint32_t bh[4], bl[4];
            ldsm_x4(bh, sBh + off);
            ldsm_x4(bl, sBl + off);
#pragma unroll
            for (int mt = 0; mt < 2; ++mt)
#pragma unroll
                for (int w = 0; w < 2; ++w)
                    mma_f16(acc[mt][np * 2 + w], ah[mt], bh[w], bh[w + 2]);
#pragma unroll
            for (int mt = 0; mt < 2; ++mt)
#pragma unroll
                for (int w = 0; w < 2; ++w)
                    mma_f16(acc[mt][np * 2 + w], ah[mt], bl[w], bl[w + 2]);
        }
    }
}

// ---------------------------------------------------------------------------
// cp.async one stage: 3 matrices x 128 rows x 64B, 6 chunks of 16B per thread
// ---------------------------------------------------------------------------
DI void stage_cp3(uint32_t sbase, const __half* A,
                  const __half* Bh, const __half* Bl,
                  int ldA, int ldB, int m0, int n0, int k0, int tid) {
    const int q = tid & 3;
    const int r = tid >> 2;
#pragma unroll
    for (int i = 0; i < 6; ++i) {
        const int mat = i >> 1;
        const int row = (i & 1) * 64 + r;
        const __half* p = (mat == 0) ? A : (mat == 1) ? Bh : Bl;
        const int ld = (mat == 0) ? ldA : ldB;
        const int r0 = (mat == 0) ? m0 : n0;
        uint32_t sa = sbase + (uint32_t)(mat * (MAT_ELE * 2) + row * (RS * 2) + q * 16);
        cp_async16(sa, p + (size_t)(r0 + row) * ld + k0 + q * 8);
    }
}

// ---------------------------------------------------------------------------
// prep: weights -> fp16 hi/lo (wo/wc transposed; lin as-is) + inv init
// ---------------------------------------------------------------------------
__global__ void prep_kernel(const float* __restrict__ wo, const float* __restrict__ wc,
                            const float* __restrict__ lw) {
    int i = blockIdx.x * 256 + threadIdx.x;   // 0 .. 512*1024-1
    int n = i >> 10;
    int k = i & 1023;

    __half h, l;
    split_f16(lw[i], h, l);                   // lin_w is [512][1024] = [n][k]
    g_lin_hi[i] = h;
    g_lin_lo[i] = l;

    if (k < 512) {
        int src = k * 512 + n;                // B[n][k] = W[k][n]
        int dst = n * 512 + k;
        split_f16(wo[src], h, l);
        g_wo_hi[dst] = h; g_wo_lo[dst] = l;
        split_f16(wc[src], h, l);
        g_wc_hi[dst] = h; g_wc_lo[dst] = l;
    }
    if (i < NNODE) { g_inv_p[i] = -1; g_inv_k[i] = -1; }
}

__global__ void inv_fill_kernel(const int* __restrict__ idxp,
                                const int* __restrict__ idxk) {
    int m = blockIdx.x * 256 + threadIdx.x;   // 0 .. MMUT-1
    g_inv_p[idxp[m]] = m;
    g_inv_k[idxk[m]] = m;
}

// ---------------------------------------------------------------------------
// split inputs: h_p, h_k fp32 -> fp16 (hi only)
// ---------------------------------------------------------------------------
__global__ void split_inputs_kernel(const float* __restrict__ hp,
                                    const float* __restrict__ hk) {
    const size_t idx = (size_t)blockIdx.x * 256 + threadIdx.x;   // float4 index
    const int z = blockIdx.y;
    const float* src = z ? hk : hp;
    __half* dh = z ? g_hk : g_hp;

    float4 v = *reinterpret_cast<const float4*>(src + idx * 4);
    __half2 a; a.x = __float2half_rn(v.x); a.y = __float2half_rn(v.y);
    __half2 b; b.x = __float2half_rn(v.z); b.y = __float2half_rn(v.w);
    uint2 u;
    u.x = *reinterpret_cast<uint32_t*>(&a);
    u.y = *reinterpret_cast<uint32_t*>(&b);
    *reinterpret_cast<uint2*>(dh + idx * 4) = u;
}

// ---------------------------------------------------------------------------
// Mainloop macro body: 3-stage ring, ONE __syncthreads per stage.
// Loads for stage s+2 are issued AFTER the sync (buffer was consumed at s-1).
// ---------------------------------------------------------------------------
#define MAINLOOP(S, LDA, LDB, Aptr, Bhptr, Blptr)                               \
    stage_cp3(sb, Aptr, Bhptr, Blptr, LDA, LDB, m0, n0, 0, tid);                \
    cp_commit();                                                                \
    stage_cp3(sb + BUF_BYTES, Aptr, Bhptr, Blptr, LDA, LDB, m0, n0, 32, tid);   \
    cp_commit();                                                                \
    {                                                                           \
        int rbuf = 0, wbuf = 2;                                                 \
        _Pragma("unroll 1")                                                     \
        for (int s = 0; s < (S); ++s) {                                         \
            if (s + 1 < (S)) cp_wait<1>(); else cp_wait<0>();                   \
            __syncthreads();                                                    \
            if (s + 2 < (S)) {                                                  \
                stage_cp3(sb + wbuf * BUF_BYTES, Aptr, Bhptr, Blptr,            \
                          LDA, LDB, m0, n0, (s + 2) * 32, tid);                 \
                cp_commit();                                                    \
                wbuf = (wbuf == 2) ? 0 : wbuf + 1;                              \
            }                                                                   \
            compute_stage(sb + rbuf * BUF_BYTES, lane, wm, wn, acc);            \
            rbuf = (rbuf == 2) ? 0 : rbuf + 1;                                  \
        }                                                                       \
    }

// ---------------------------------------------------------------------------
// GEMM1 (one z half per launch): trans = h @ W  (fp16 2-product).
// Fused epilogue: mutual rows -> tanh -> fp16 into g_g; others -> d_out.
// grid (4 n-tiles, 512 m-tiles), block 256, 2 CTAs/SM
// ---------------------------------------------------------------------------
__global__ __launch_bounds__(256, 2) void gemm1_kernel(float* __restrict__ out,
                                                       int z) {
    extern __shared__ __align__(16) __half sm[];
    const int tid = threadIdx.x, lane = tid & 31, wid = tid >> 5;
    const int wm = wid & 3, wn = wid >> 2;
    const int n0 = blockIdx.x * 128, m0 = blockIdx.y * 128;

    const __half* A  = z ? g_hk : g_hp;
    const __half* Bh = z ? g_wc_hi : g_wo_hi;
    const __half* Bl = z ? g_wc_lo : g_wo_lo;
    const int* inv = z ? g_inv_k : g_inv_p;
    float* dst = out + (size_t)z * NNODE * DIM;
    const int coff = z ? DIM : 0;          // column offset into g (concat)

    float acc[2][8][4];
#pragma unroll
    for (int i = 0; i < 2; ++i)
#pragma unroll
        for (int j = 0; j < 8; ++j)
#pragma unroll
            for (int k = 0; k < 4; ++k) acc[i][j][k] = 0.f;

    const uint32_t sb = smem_u32(sm);

    MAINLOOP(DIM / 32, DIM, DIM, A, Bh, Bl)

    // Epilogue: per accumulator row, route to g (mutual) or d_out (plain)
#pragma unroll
    for (int mt = 0; mt < 2; ++mt) {
#pragma unroll
        for (int r = 0; r < 2; ++r) {
            const int row = m0 + wm * 32 + mt * 16 + (lane >> 2) + r * 8;
            const int m = inv[row];
            if (m >= 0) {
                __half* gp = g_g + (size_t)m * (2 * DIM) + coff;
#pragma unroll
                for (int nt = 0; nt < 8; ++nt) {
                    int gcol = n0 + wn * 64 + nt * 8 + (lane & 3) * 2;
                    __half2 hv;
                    hv.x = __float2half_rn(tanhf(acc[mt][nt][r * 2 + 0]));
                    hv.y = __float2half_rn(tanhf(acc[mt][nt][r * 2 + 1]));
                    *reinterpret_cast<__half2*>(gp + gcol) = hv;
                }
            } else {
                float* rp = dst + (size_t)row * DIM;
#pragma unroll
                for (int nt = 0; nt < 8; ++nt) {
                    int gcol = n0 + wn * 64 + nt * 8 + (lane & 3) * 2;
                    float2 v;
                    v.x = acc[mt][nt][r * 2 + 0];
                    v.y = acc[mt][nt][r * 2 + 1];
                    *reinterpret_cast<float2*>(rp + gcol) = v;
                }
            }
        }
    }
}

// ---------------------------------------------------------------------------
// GEMM2: rows = leaky_relu(g @ lin_w^T + lin_b) + bias, scattered into both
//        halves of d_out.  fp16 2-product.
// grid (4 n-tiles, 256 m-tiles), block 256, 2 CTAs/SM
// ---------------------------------------------------------------------------
__global__ __launch_bounds__(256, 2) void gemm2_kernel(
    const int* __restrict__ idxp, const int* __restrict__ idxk,
    const float* __restrict__ lin_b, const float* __restrict__ bias,
    float* __restrict__ out) {
    extern __shared__ __align__(16) __half sm[];
    const int tid = threadIdx.x, lane = tid & 31, wid = tid >> 5;
    const int wm = wid & 3, wn = wid >> 2;
    const int n0 = blockIdx.x * 128, m0 = blockIdx.y * 128;

    float* outp = out;
    float* outk = out + (size_t)NNODE * DIM;

    float acc[2][8][4];
#pragma unroll
    for (int i = 0; i < 2; ++i)
#pragma unroll
        for (int j = 0; j < 8; ++j)
#pragma unroll
            for (int k = 0; k < 4; ++k) acc[i][j][k] = 0.f;

    const uint32_t sb = smem_u32(sm);

    MAINLOOP((2 * DIM) / 32, 2 * DIM, 2 * DIM, g_g, g_lin_hi, g_lin_lo)

#pragma unroll
    for (int mt = 0; mt < 2; ++mt) {
        int grow = m0 + wm * 32 + mt * 16 + (lane >> 2);
        int p0 = idxp[grow], p1 = idxp[grow + 8];
        int q0 = idxk[grow], q1 = idxk[grow + 8];
#pragma unroll
        for (int nt = 0; nt < 8; ++nt) {
            int gcol = n0 + wn * 64 + nt * 8 + (lane & 3) * 2;
            float2 lb = *reinterpret_cast<const float2*>(lin_b + gcol);
            float2 bs = *reinterpret_cast<const float2*>(bias + gcol);
            float x0 = acc[mt][nt][0] + lb.x;
            float x1 = acc[mt][nt][1] + lb.y;
            float x2 = acc[mt][nt][2] + lb.x;
            float x3 = acc[mt][nt][3] + lb.y;
            x0 = (x0 >= 0.f ? x0 : 0.01f * x0) + bs.x;
            x1 = (x1 >= 0.f ? x1 : 0.01f * x1) + bs.y;
            x2 = (x2 >= 0.f ? x2 : 0.01f * x2) + bs.x;
            x3 = (x3 >= 0.f ? x3 : 0.01f * x3) + bs.y;
            float2 v0; v0.x = x0; v0.y = x1;
            float2 v1; v1.x = x2; v1.y = x3;
            *reinterpret_cast<float2*>(outp + (size_t)p0 * DIM + gcol) = v0;
            *reinterpret_cast<float2*>(outp + (size_t)p1 * DIM + gcol) = v1;
            *reinterpret_cast<float2*>(outk + (size_t)q0 * DIM + gcol) = v0;
            *reinterpret_cast<float2*>(outk + (size_t)q1 * DIM + gcol) = v1;
        }
    }
}

// ---------------------------------------------------------------------------
// Launch
// ---------------------------------------------------------------------------
extern "C" void kernel_launch(void* const* d_in, const int* in_sizes, int n_in,
                              void* d_out, int out_size) {
    const float* h_p  = (const float*)d_in[0];
    const float* h_k  = (const float*)d_in[1];
    const int*   idxp = (const int*)d_in[2];
    const int*   idxk = (const int*)d_in[3];
    // d_in[4] = last_x (unused by the reference computation)
    const float* wo   = (const float*)d_in[5];
    const float* wc   = (const float*)d_in[6];
    const float* lw   = (const float*)d_in[7];
    const float* lb   = (const float*)d_in[8];
    const float* bias = (const float*)d_in[9];
    float* out = (float*)d_out;

    cudaFuncSetAttribute(gemm1_kernel, cudaFuncAttributeMaxDynamicSharedMemorySize, SMEM_BYTES);
    cudaFuncSetAttribute(gemm2_kernel, cudaFuncAttributeMaxDynamicSharedMemorySize, SMEM_BYTES);

    prep_kernel<<<(512 * 1024) / 256, 256>>>(wo, wc, lw);

    inv_fill_kernel<<<MMUT / 256, 256>>>(idxp, idxk);

    split_inputs_kernel<<<dim3((NNODE * DIM / 4) / 256, 2), 256>>>(h_p, h_k);

    gemm1_kernel<<<dim3(DIM / 128, NNODE / 128), 256, SMEM_BYTES>>>(out, 0);
    gemm1_kernel<<<dim3(DIM / 128, NNODE / 128), 256, SMEM_BYTES>>>(out, 1);

    gemm2_kernel<<<dim3(DIM / 128, MMUT / 128), 256, SMEM_BYTES>>>(idxp, idxk, lb, bias, out);
}

// round 14
// speedup vs baseline: 1.5989x; 1.0750x over previous
#include <cuda_runtime.h>
#include <cuda_bf16.h>
#include <cuda_fp16.h>
#include <cstdint>

// ---------------------------------------------------------------------------
// Problem constants
// ---------------------------------------------------------------------------
#define DIM   512
#define NNODE 65536
#define MMUT  32768

// ---------------------------------------------------------------------------
// Smem tile geometry: CTA tile 128x128, K-stage 64, rows padded to 72 halves
// (144 B row stride -> 36 banks mod 32 = 4: ldmatrix 8-row phases conflict-free)
// 3 matrices per stage (A, B_hi, B_lo), 2-stage ring buffer
// ---------------------------------------------------------------------------
#define KS      64
#define RS      72                    // row stride in 2B elems (144 bytes)
#define MAT_ELE (128 * RS)            // one 128x64(+pad) matrix = 9216 elems
#define BUF_BYTES (3 * MAT_ELE * 2)   // 55296 per stage
#define SMEM_BYTES (2 * BUF_BYTES)    // 110592 (double buffered)

#define DI __device__ __forceinline__

// ---------------------------------------------------------------------------
// Device scratch (__device__ globals only — no allocations)
// ---------------------------------------------------------------------------
// GEMM1 weights: fp16 hi/lo, transposed to [n][k]
__device__ __half g_wo_hi[DIM * DIM];
__device__ __half g_wo_lo[DIM * DIM];
__device__ __half g_wc_hi[DIM * DIM];
__device__ __half g_wc_lo[DIM * DIM];
// GEMM2 weights: fp16 hi/lo, [n=512][k=1024]
__device__ __half g_lin_hi[DIM * 2 * DIM];
__device__ __half g_lin_lo[DIM * 2 * DIM];
// inputs: h_p, h_k as fp16 (hi only — 2-product scheme)
__device__ __half g_hp[(size_t)NNODE * DIM];
__device__ __half g_hk[(size_t)NNODE * DIM];
// gathered + tanh'd GEMM2 A matrix: [MMUT, 1024] fp16 (hi only)
__device__ __half g_g[(size_t)MMUT * 2 * DIM];
// inverse index maps: node -> mutual position (or -1)
__device__ int g_inv_p[NNODE];
__device__ int g_inv_k[NNODE];

// ---------------------------------------------------------------------------
// Helpers
// ---------------------------------------------------------------------------
DI uint32_t smem_u32(const void* p) {
    uint32_t a;
    asm("{ .reg .u64 t; cvta.to.shared.u64 t, %1; cvt.u32.u64 %0, t; }"
        : "=r"(a) : "l"(p));
    return a;
}

DI void split_f16(float v, __half& h, __half& l) {
    h = __float2half_rn(v);
    l = __float2half_rn(v - __half2float(h));
}

DI void ldsm_x4(uint32_t* r, uint32_t addr) {
    asm volatile("ldmatrix.sync.aligned.m8n8.x4.shared.b16 {%0,%1,%2,%3}, [%4];"
                 : "=r"(r[0]), "=r"(r[1]), "=r"(r[2]), "=r"(r[3]) : "r"(addr));
}

DI void mma_f16(float* c, const uint32_t* a, uint32_t b0, uint32_t b1) {
    asm volatile(
        "mma.sync.aligned.m16n8k16.row.col.f32.f16.f16.f32 "
        "{%0,%1,%2,%3}, {%4,%5,%6,%7}, {%8,%9}, {%0,%1,%2,%3};"
        : "+f"(c[0]), "+f"(c[1]), "+f"(c[2]), "+f"(c[3])
        : "r"(a[0]), "r"(a[1]), "r"(a[2]), "r"(a[3]), "r"(b0), "r"(b1));
}

DI void cp_async16(uint32_t saddr, const void* gptr) {
    asm volatile("cp.async.cg.shared.global [%0], [%1], 16;"
                 :: "r"(saddr), "l"(gptr));
}
DI void cp_commit() { asm volatile("cp.async.commit_group;" ::: "memory"); }
template <int N> DI void cp_wait() {
    asm volatile("cp.async.wait_group %0;" :: "n"(N) : "memory");
}

// ---------------------------------------------------------------------------
// One K-stage (64): fp16 2-product, warp tile 32x64, 4 k16 steps.
// C = A_hi*B_hi + A_hi*B_lo  (dropped A_lo*B ~ 2^-12 relative)
// ---------------------------------------------------------------------------
DI void compute_stage(uint32_t base, int lane, int wm, int wn,
                      float acc[2][8][4]) {
    const uint32_t sA  = base;
    const uint32_t sBh = base + MAT_ELE * 2;
    const uint32_t sBl = base + MAT_ELE * 4;
    const int lrow = lane & 15;
    const int lkh  = lane >> 4;
#pragma unroll
    for (int ks = 0; ks < 4; ++ks) {
        const uint32_t kbyte = (uint32_t)(ks * 16 + 8 * lkh) * 2;
        uint32_t ah[2][4];
#pragma unroll
        for (int mt = 0; mt < 2; ++mt) {
            uint32_t off = (uint32_t)((wm * 32 + mt * 16 + lrow) * (RS * 2)) + kbyte;
            ldsm_x4(ah[mt], sA + off);
        }
#pragma unroll
        for (int np = 0; np < 4; ++np) {
            uint32_t off = (uint32_t)((wn * 64 + np * 16 + lrow) * (RS * 2)) + kbyte;
            uint32_t bh[4], bl[4];
            ldsm_x4(bh, sBh + off);
            ldsm_x4(bl, sBl + off);
#pragma unroll
            for (int mt = 0; mt < 2; ++mt)
#pragma unroll
                for (int w = 0; w < 2; ++w)
                    mma_f16(acc[mt][np * 2 + w], ah[mt], bh[w], bh[w + 2]);
#pragma unroll
            for (int mt = 0; mt < 2; ++mt)
#pragma unroll
                for (int w = 0; w < 2; ++w)
                    mma_f16(acc[mt][np * 2 + w], ah[mt], bl[w], bl[w + 2]);
        }
    }
}

// ---------------------------------------------------------------------------
// cp.async one stage: 3 matrices x 128 rows x 128B, 12 chunks of 16B / thread
// ---------------------------------------------------------------------------
DI void stage_cp3(uint32_t sbase, const __half* A,
                  const __half* Bh, const __half* Bl,
                  int ldA, int ldB, int m0, int n0, int k0, int tid) {
    const int q = tid & 7;        // 16B chunk within 128B row
    const int r = tid >> 3;       // 0..31
#pragma unroll
    for (int i = 0; i < 12; ++i) {
        const int mat = i >> 2;                   // 0:A 1:B_hi 2:B_lo
        const int row = (i & 3) * 32 + r;
        const __half* p = (mat == 0) ? A : (mat == 1) ? Bh : Bl;
        const int ld = (mat == 0) ? ldA : ldB;
        const int r0 = (mat == 0) ? m0 : n0;
        uint32_t sa = sbase + (uint32_t)(mat * (MAT_ELE * 2) + row * (RS * 2) + q * 16);
        cp_async16(sa, p + (size_t)(r0 + row) * ld + k0 + q * 8);
    }
}

// ---------------------------------------------------------------------------
// prep: weights -> fp16 hi/lo (wo/wc transposed; lin as-is) + inv init
// ---------------------------------------------------------------------------
__global__ void prep_kernel(const float* __restrict__ wo, const float* __restrict__ wc,
                            const float* __restrict__ lw) {
    int i = blockIdx.x * 256 + threadIdx.x;   // 0 .. 512*1024-1
    int n = i >> 10;
    int k = i & 1023;

    __half h, l;
    split_f16(lw[i], h, l);                   // lin_w is [512][1024] = [n][k]
    g_lin_hi[i] = h;
    g_lin_lo[i] = l;

    if (k < 512) {
        int src = k * 512 + n;                // B[n][k] = W[k][n]
        int dst = n * 512 + k;
        split_f16(wo[src], h, l);
        g_wo_hi[dst] = h; g_wo_lo[dst] = l;
        split_f16(wc[src], h, l);
        g_wc_hi[dst] = h; g_wc_lo[dst] = l;
    }
    if (i < NNODE) { g_inv_p[i] = -1; g_inv_k[i] = -1; }
}

__global__ void inv_fill_kernel(const int* __restrict__ idxp,
                                const int* __restrict__ idxk) {
    int m = blockIdx.x * 256 + threadIdx.x;   // 0 .. MMUT-1
    g_inv_p[idxp[m]] = m;
    g_inv_k[idxk[m]] = m;
}

// ---------------------------------------------------------------------------
// split inputs: h_p, h_k fp32 -> fp16 (hi only)
// ---------------------------------------------------------------------------
__global__ void split_inputs_kernel(const float* __restrict__ hp,
                                    const float* __restrict__ hk) {
    const size_t idx = (size_t)blockIdx.x * 256 + threadIdx.x;   // float4 index
    const int z = blockIdx.y;
    const float* src = z ? hk : hp;
    __half* dh = z ? g_hk : g_hp;

    float4 v = *reinterpret_cast<const float4*>(src + idx * 4);
    __half2 a; a.x = __float2half_rn(v.x); a.y = __float2half_rn(v.y);
    __half2 b; b.x = __float2half_rn(v.z); b.y = __float2half_rn(v.w);
    uint2 u;
    u.x = *reinterpret_cast<uint32_t*>(&a);
    u.y = *reinterpret_cast<uint32_t*>(&b);
    *reinterpret_cast<uint2*>(dh + idx * 4) = u;
}

// ---------------------------------------------------------------------------
// Mainloop: 2-stage ring, ONE __syncthreads per stage.
// At stage s only load s is outstanding; wait it, barrier (publishes smem and
// frees buffer (s+1)&1, consumed at s-1), issue load s+1, compute s.
// ---------------------------------------------------------------------------
#define MAINLOOP(S, LDA, LDB, Aptr, Bhptr, Blptr)                               \
    stage_cp3(sb, Aptr, Bhptr, Blptr, LDA, LDB, m0, n0, 0, tid);                \
    cp_commit();                                                                \
    _Pragma("unroll 1")                                                         \
    for (int s = 0; s < (S); ++s) {                                             \
        cp_wait<0>();                                                           \
        __syncthreads();                                                        \
        if (s + 1 < (S)) {                                                      \
            stage_cp3(sb + ((s + 1) & 1) * BUF_BYTES, Aptr, Bhptr, Blptr,       \
                      LDA, LDB, m0, n0, (s + 1) * KS, tid);                     \
            cp_commit();                                                        \
        }                                                                       \
        compute_stage(sb + (s & 1) * BUF_BYTES, lane, wm, wn, acc);             \
    }

// ---------------------------------------------------------------------------
// GEMM1 (one z half per launch): trans = h @ W  (fp16 2-product).
// Fused epilogue: mutual rows -> tanh -> fp16 into g_g; others -> d_out.
// grid (4 n-tiles, 512 m-tiles), block 256, 2 CTAs/SM
// ---------------------------------------------------------------------------
__global__ __launch_bounds__(256, 2) void gemm1_kernel(float* __restrict__ out,
                                                       int z) {
    extern __shared__ __align__(16) __half sm[];
    const int tid = threadIdx.x, lane = tid & 31, wid = tid >> 5;
    const int wm = wid & 3, wn = wid >> 2;
    const int n0 = blockIdx.x * 128, m0 = blockIdx.y * 128;

    const __half* A  = z ? g_hk : g_hp;
    const __half* Bh = z ? g_wc_hi : g_wo_hi;
    const __half* Bl = z ? g_wc_lo : g_wo_lo;
    const int* inv = z ? g_inv_k : g_inv_p;
    float* dst = out + (size_t)z * NNODE * DIM;
    const int coff = z ? DIM : 0;          // column offset into g (concat)

    float acc[2][8][4];
#pragma unroll
    for (int i = 0; i < 2; ++i)
#pragma unroll
        for (int j = 0; j < 8; ++j)
#pragma unroll
            for (int k = 0; k < 4; ++k) acc[i][j][k] = 0.f;

    const uint32_t sb = smem_u32(sm);

    MAINLOOP(DIM / KS, DIM, DIM, A, Bh, Bl)

    // Epilogue: per accumulator row, route to g (mutual) or d_out (plain)
#pragma unroll
    for (int mt = 0; mt < 2; ++mt) {
#pragma unroll
        for (int r = 0; r < 2; ++r) {
            const int row = m0 + wm * 32 + mt * 16 + (lane >> 2) + r * 8;
            const int m = inv[row];
            if (m >= 0) {
                __half* gp = g_g + (size_t)m * (2 * DIM) + coff;
#pragma unroll
                for (int nt = 0; nt < 8; ++nt) {
                    int gcol = n0 + wn * 64 + nt * 8 + (lane & 3) * 2;
                    __half2 hv;
                    hv.x = __float2half_rn(tanhf(acc[mt][nt][r * 2 + 0]));
                    hv.y = __float2half_rn(tanhf(acc[mt][nt][r * 2 + 1]));
                    *reinterpret_cast<__half2*>(gp + gcol) = hv;
                }
            } else {
                float* rp = dst + (size_t)row * DIM;
#pragma unroll
                for (int nt = 0; nt < 8; ++nt) {
                    int gcol = n0 + wn * 64 + nt * 8 + (lane & 3) * 2;
                    float2 v;
                    v.x = acc[mt][nt][r * 2 + 0];
                    v.y = acc[mt][nt][r * 2 + 1];
                    *reinterpret_cast<float2*>(rp + gcol) = v;
                }
            }
        }
    }
}

// ---------------------------------------------------------------------------
// GEMM2: rows = leaky_relu(g @ lin_w^T + lin_b) + bias, scattered into both
//        halves of d_out.  fp16 2-product.
// grid (4 n-tiles, 256 m-tiles), block 256, 2 CTAs/SM
// ---------------------------------------------------------------------------
__global__ __launch_bounds__(256, 2) void gemm2_kernel(
    const int* __restrict__ idxp, const int* __restrict__ idxk,
    const float* __restrict__ lin_b, const float* __restrict__ bias,
    float* __restrict__ out) {
    extern __shared__ __align__(16) __half sm[];
    const int tid = threadIdx.x, lane = tid & 31, wid = tid >> 5;
    const int wm = wid & 3, wn = wid >> 2;
    const int n0 = blockIdx.x * 128, m0 = blockIdx.y * 128;

    float* outp = out;
    float* outk = out + (size_t)NNODE * DIM;

    float acc[2][8][4];
#pragma unroll
    for (int i = 0; i < 2; ++i)
#pragma unroll
        for (int j = 0; j < 8; ++j)
#pragma unroll
            for (int k = 0; k < 4; ++k) acc[i][j][k] = 0.f;

    const uint32_t sb = smem_u32(sm);

    MAINLOOP((2 * DIM) / KS, 2 * DIM, 2 * DIM, g_g, g_lin_hi, g_lin_lo)

#pragma unroll
    for (int mt = 0; mt < 2; ++mt) {
        int grow = m0 + wm * 32 + mt * 16 + (lane >> 2);
        int p0 = idxp[grow], p1 = idxp[grow + 8];
        int q0 = idxk[grow], q1 = idxk[grow + 8];
#pragma unroll
        for (int nt = 0; nt < 8; ++nt) {
            int gcol = n0 + wn * 64 + nt * 8 + (lane & 3) * 2;
            float2 lb = *reinterpret_cast<const float2*>(lin_b + gcol);
            float2 bs = *reinterpret_cast<const float2*>(bias + gcol);
            float x0 = acc[mt][nt][0] + lb.x;
            float x1 = acc[mt][nt][1] + lb.y;
            float x2 = acc[mt][nt][2] + lb.x;
            float x3 = acc[mt][nt][3] + lb.y;
            x0 = (x0 >= 0.f ? x0 : 0.01f * x0) + bs.x;
            x1 = (x1 >= 0.f ? x1 : 0.01f * x1) + bs.y;
            x2 = (x2 >= 0.f ? x2 : 0.01f * x2) + bs.x;
            x3 = (x3 >= 0.f ? x3 : 0.01f * x3) + bs.y;
            float2 v0; v0.x = x0; v0.y = x1;
            float2 v1; v1.x = x2; v1.y = x3;
            *reinterpret_cast<float2*>(outp + (size_t)p0 * DIM + gcol) = v0;
            *reinterpret_cast<float2*>(outp + (size_t)p1 * DIM + gcol) = v1;
            *reinterpret_cast<float2*>(outk + (size_t)q0 * DIM + gcol) = v0;
            *reinterpret_cast<float2*>(outk + (size_t)q1 * DIM + gcol) = v1;
        }
    }
}

// ---------------------------------------------------------------------------
// Launch
// ---------------------------------------------------------------------------
extern "C" void kernel_launch(void* const* d_in, const int* in_sizes, int n_in,
                              void* d_out, int out_size) {
    const float* h_p  = (const float*)d_in[0];
    const float* h_k  = (const float*)d_in[1];
    const int*   idxp = (const int*)d_in[2];
    const int*   idxk = (const int*)d_in[3];
    // d_in[4] = last_x (unused by the reference computation)
    const float* wo   = (const float*)d_in[5];
    const float* wc   = (const float*)d_in[6];
    const float* lw   = (const float*)d_in[7];
    const float* lb   = (const float*)d_in[8];
    const float* bias = (const float*)d_in[9];
    float* out = (float*)d_out;

    cudaFuncSetAttribute(gemm1_kernel, cudaFuncAttributeMaxDynamicSharedMemorySize, SMEM_BYTES);
    cudaFuncSetAttribute(gemm2_kernel, cudaFuncAttributeMaxDynamicSharedMemorySize, SMEM_BYTES);

    prep_kernel<<<(512 * 1024) / 256, 256>>>(wo, wc, lw);

    inv_fill_kernel<<<MMUT / 256, 256>>>(idxp, idxk);

    split_inputs_kernel<<<dim3((NNODE * DIM / 4) / 256, 2), 256>>>(h_p, h_k);

    gemm1_kernel<<<dim3(DIM / 128, NNODE / 128), 256, SMEM_BYTES>>>(out, 0);
    gemm1_kernel<<<dim3(DIM / 128, NNODE / 128), 256, SMEM_BYTES>>>(out, 1);

    gemm2_kernel<<<dim3(DIM / 128, MMUT / 128), 256, SMEM_BYTES>>>(idxp, idxk, lb, bias, out);
}

// round 15
// speedup vs baseline: 2.4813x; 1.5519x over previous
#include <cuda_runtime.h>
#include <cuda_bf16.h>
#include <cuda_fp16.h>
#include <cstdint>

// ---------------------------------------------------------------------------
// Problem constants
// ---------------------------------------------------------------------------
#define DIM   512
#define NNODE 65536
#define MMUT  32768

// ---------------------------------------------------------------------------
// Smem tile geometry: CTA tile 128x128, K-stage 64, rows padded to 72 halves
// (144 B row stride -> 36 banks mod 32 = 4: ldmatrix 8-row phases conflict-free)
// 2 matrices per stage (A, B), 2-stage ring buffer
// ---------------------------------------------------------------------------
#define KS      64
#define RS      72                    // row stride in 2B elems (144 bytes)
#define MAT_ELE (128 * RS)            // one 128x64(+pad) matrix = 9216 elems
#define BUF_BYTES (2 * MAT_ELE * 2)   // 36864 per stage
#define SMEM_BYTES (2 * BUF_BYTES)    // 73728 (double buffered)

#define DI __device__ __forceinline__

// ---------------------------------------------------------------------------
// Device scratch (__device__ globals only — no allocations)
// ---------------------------------------------------------------------------
// GEMM1 weights: fp16, transposed to [n][k]
__device__ __half g_wo[DIM * DIM];
__device__ __half g_wc[DIM * DIM];
// GEMM2 weights: fp16, [n=512][k=1024]
__device__ __half g_lin[DIM * 2 * DIM];
// inputs: h_p, h_k as fp16
__device__ __half g_hp[(size_t)NNODE * DIM];
__device__ __half g_hk[(size_t)NNODE * DIM];
// gathered + tanh'd GEMM2 A matrix: [MMUT, 1024] fp16
__device__ __half g_g[(size_t)MMUT * 2 * DIM];
// inverse index maps: node -> mutual position (or -1)
__device__ int g_inv_p[NNODE];
__device__ int g_inv_k[NNODE];

// ---------------------------------------------------------------------------
// Helpers
// ---------------------------------------------------------------------------
DI uint32_t smem_u32(const void* p) {
    uint32_t a;
    asm("{ .reg .u64 t; cvta.to.shared.u64 t, %1; cvt.u32.u64 %0, t; }"
        : "=r"(a) : "l"(p));
    return a;
}

DI void ldsm_x4(uint32_t* r, uint32_t addr) {
    asm volatile("ldmatrix.sync.aligned.m8n8.x4.shared.b16 {%0,%1,%2,%3}, [%4];"
                 : "=r"(r[0]), "=r"(r[1]), "=r"(r[2]), "=r"(r[3]) : "r"(addr));
}

DI void mma_f16(float* c, const uint32_t* a, uint32_t b0, uint32_t b1) {
    asm volatile(
        "mma.sync.aligned.m16n8k16.row.col.f32.f16.f16.f32 "
        "{%0,%1,%2,%3}, {%4,%5,%6,%7}, {%8,%9}, {%0,%1,%2,%3};"
        : "+f"(c[0]), "+f"(c[1]), "+f"(c[2]), "+f"(c[3])
        : "r"(a[0]), "r"(a[1]), "r"(a[2]), "r"(a[3]), "r"(b0), "r"(b1));
}

DI void cp_async16(uint32_t saddr, const void* gptr) {
    asm volatile("cp.async.cg.shared.global [%0], [%1], 16;"
                 :: "r"(saddr), "l"(gptr));
}
DI void cp_commit() { asm volatile("cp.async.commit_group;" ::: "memory"); }
template <int N> DI void cp_wait() {
    asm volatile("cp.async.wait_group %0;" :: "n"(N) : "memory");
}

// ---------------------------------------------------------------------------
// One K-stage (64): plain fp16, warp tile 32x64, 4 k16 steps.
// ---------------------------------------------------------------------------
DI void compute_stage(uint32_t base, int lane, int wm, int wn,
                      float acc[2][8][4]) {
    const uint32_t sA = base;
    const uint32_t sB = base + MAT_ELE * 2;
    const int lrow = lane & 15;
    const int lkh  = lane >> 4;
#pragma unroll
    for (int ks = 0; ks < 4; ++ks) {
        const uint32_t kbyte = (uint32_t)(ks * 16 + 8 * lkh) * 2;
        uint32_t ah[2][4];
#pragma unroll
        for (int mt = 0; mt < 2; ++mt) {
            uint32_t off = (uint32_t)((wm * 32 + mt * 16 + lrow) * (RS * 2)) + kbyte;
            ldsm_x4(ah[mt], sA + off);
        }
#pragma unroll
        for (int np = 0; np < 4; ++np) {
            uint32_t off = (uint32_t)((wn * 64 + np * 16 + lrow) * (RS * 2)) + kbyte;
            uint32_t bh[4];
            ldsm_x4(bh, sB + off);
#pragma unroll
            for (int mt = 0; mt < 2; ++mt)
#pragma unroll
                for (int w = 0; w < 2; ++w)
                    mma_f16(acc[mt][np * 2 + w], ah[mt], bh[w], bh[w + 2]);
        }
    }
}

// ---------------------------------------------------------------------------
// cp.async one stage: 2 matrices x 128 rows x 128B, 8 chunks of 16B / thread
// ---------------------------------------------------------------------------
DI void stage_cp2(uint32_t sbase, const __half* A, const __half* B,
                  int ldA, int ldB, int m0, int n0, int k0, int tid) {
    const int q = tid & 7;        // 16B chunk within 128B row
    const int r = tid >> 3;       // 0..31
#pragma unroll
    for (int i = 0; i < 8; ++i) {
        const int mat = i >> 2;                   // 0:A 1:B
        const int row = (i & 3) * 32 + r;
        const __half* p = (mat == 0) ? A : B;
        const int ld = (mat == 0) ? ldA : ldB;
        const int r0 = (mat == 0) ? m0 : n0;
        uint32_t sa = sbase + (uint32_t)(mat * (MAT_ELE * 2) + row * (RS * 2) + q * 16);
        cp_async16(sa, p + (size_t)(r0 + row) * ld + k0 + q * 8);
    }
}

// ---------------------------------------------------------------------------
// prep: weights -> fp16 (wo/wc transposed; lin as-is) + inv init
// ---------------------------------------------------------------------------
__global__ void prep_kernel(const float* __restrict__ wo, const float* __restrict__ wc,
                            const float* __restrict__ lw) {
    int i = blockIdx.x * 256 + threadIdx.x;   // 0 .. 512*1024-1
    int n = i >> 10;
    int k = i & 1023;

    g_lin[i] = __float2half_rn(lw[i]);        // lin_w is [512][1024] = [n][k]

    if (k < 512) {
        int src = k * 512 + n;                // B[n][k] = W[k][n]
        int dst = n * 512 + k;
        g_wo[dst] = __float2half_rn(wo[src]);
        g_wc[dst] = __float2half_rn(wc[src]);
    }
    if (i < NNODE) { g_inv_p[i] = -1; g_inv_k[i] = -1; }
}

__global__ void inv_fill_kernel(const int* __restrict__ idxp,
                                const int* __restrict__ idxk) {
    int m = blockIdx.x * 256 + threadIdx.x;   // 0 .. MMUT-1
    g_inv_p[idxp[m]] = m;
    g_inv_k[idxk[m]] = m;
}

// ---------------------------------------------------------------------------
// split inputs: h_p, h_k fp32 -> fp16
// ---------------------------------------------------------------------------
__global__ void split_inputs_kernel(const float* __restrict__ hp,
                                    const float* __restrict__ hk) {
    const size_t idx = (size_t)blockIdx.x * 256 + threadIdx.x;   // float4 index
    const int z = blockIdx.y;
    const float* src = z ? hk : hp;
    __half* dh = z ? g_hk : g_hp;

    float4 v = *reinterpret_cast<const float4*>(src + idx * 4);
    __half2 a; a.x = __float2half_rn(v.x); a.y = __float2half_rn(v.y);
    __half2 b; b.x = __float2half_rn(v.z); b.y = __float2half_rn(v.w);
    uint2 u;
    u.x = *reinterpret_cast<uint32_t*>(&a);
    u.y = *reinterpret_cast<uint32_t*>(&b);
    *reinterpret_cast<uint2*>(dh + idx * 4) = u;
}

// ---------------------------------------------------------------------------
// Mainloop: 2-stage ring, ONE __syncthreads per stage.
// ---------------------------------------------------------------------------
#define MAINLOOP(S, LDA, LDB, Aptr, Bptr)                                       \
    stage_cp2(sb, Aptr, Bptr, LDA, LDB, m0, n0, 0, tid);                        \
    cp_commit();                                                                \
    _Pragma("unroll 1")                                                         \
    for (int s = 0; s < (S); ++s) {                                             \
        cp_wait<0>();                                                           \
        __syncthreads();                                                        \
        if (s + 1 < (S)) {                                                      \
            stage_cp2(sb + ((s + 1) & 1) * BUF_BYTES, Aptr, Bptr,               \
                      LDA, LDB, m0, n0, (s + 1) * KS, tid);                     \
            cp_commit();                                                        \
        }                                                                       \
        compute_stage(sb + (s & 1) * BUF_BYTES, lane, wm, wn, acc);             \
    }

// ---------------------------------------------------------------------------
// GEMM1 (one z half per launch): trans = h @ W  (plain fp16).
// Fused epilogue: mutual rows -> tanh -> fp16 into g_g; others -> d_out.
// grid (4 n-tiles, 512 m-tiles), block 256, 2 CTAs/SM
// ---------------------------------------------------------------------------
__global__ __launch_bounds__(256, 2) void gemm1_kernel(float* __restrict__ out,
                                                       int z) {
    extern __shared__ __align__(16) __half sm[];
    const int tid = threadIdx.x, lane = tid & 31, wid = tid >> 5;
    const int wm = wid & 3, wn = wid >> 2;
    const int n0 = blockIdx.x * 128, m0 = blockIdx.y * 128;

    const __half* A = z ? g_hk : g_hp;
    const __half* B = z ? g_wc : g_wo;
    const int* inv = z ? g_inv_k : g_inv_p;
    float* dst = out + (size_t)z * NNODE * DIM;
    const int coff = z ? DIM : 0;          // column offset into g (concat)

    float acc[2][8][4];
#pragma unroll
    for (int i = 0; i < 2; ++i)
#pragma unroll
        for (int j = 0; j < 8; ++j)
#pragma unroll
            for (int k = 0; k < 4; ++k) acc[i][j][k] = 0.f;

    const uint32_t sb = smem_u32(sm);

    MAINLOOP(DIM / KS, DIM, DIM, A, B)

    // Epilogue: per accumulator row, route to g (mutual) or d_out (plain)
#pragma unroll
    for (int mt = 0; mt < 2; ++mt) {
#pragma unroll
        for (int r = 0; r < 2; ++r) {
            const int row = m0 + wm * 32 + mt * 16 + (lane >> 2) + r * 8;
            const int m = inv[row];
            if (m >= 0) {
                __half* gp = g_g + (size_t)m * (2 * DIM) + coff;
#pragma unroll
                for (int nt = 0; nt < 8; ++nt) {
                    int gcol = n0 + wn * 64 + nt * 8 + (lane & 3) * 2;
                    __half2 hv;
                    hv.x = __float2half_rn(tanhf(acc[mt][nt][r * 2 + 0]));
                    hv.y = __float2half_rn(tanhf(acc[mt][nt][r * 2 + 1]));
                    *reinterpret_cast<__half2*>(gp + gcol) = hv;
                }
            } else {
                float* rp = dst + (size_t)row * DIM;
#pragma unroll
                for (int nt = 0; nt < 8; ++nt) {
                    int gcol = n0 + wn * 64 + nt * 8 + (lane & 3) * 2;
                    float2 v;
                    v.x = acc[mt][nt][r * 2 + 0];
                    v.y = acc[mt][nt][r * 2 + 1];
                    *reinterpret_cast<float2*>(rp + gcol) = v;
                }
            }
        }
    }
}

// ---------------------------------------------------------------------------
// GEMM2: rows = leaky_relu(g @ lin_w^T + lin_b) + bias, scattered into both
//        halves of d_out.  plain fp16.
// grid (4 n-tiles, 256 m-tiles), block 256, 2 CTAs/SM
// ---------------------------------------------------------------------------
__global__ __launch_bounds__(256, 2) void gemm2_kernel(
    const int* __restrict__ idxp, const int* __restrict__ idxk,
    const float* __restrict__ lin_b, const float* __restrict__ bias,
    float* __restrict__ out) {
    extern __shared__ __align__(16) __half sm[];
    const int tid = threadIdx.x, lane = tid & 31, wid = tid >> 5;
    const int wm = wid & 3, wn = wid >> 2;
    const int n0 = blockIdx.x * 128, m0 = blockIdx.y * 128;

    float* outp = out;
    float* outk = out + (size_t)NNODE * DIM;

    float acc[2][8][4];
#pragma unroll
    for (int i = 0; i < 2; ++i)
#pragma unroll
        for (int j = 0; j < 8; ++j)
#pragma unroll
            for (int k = 0; k < 4; ++k) acc[i][j][k] = 0.f;

    const uint32_t sb = smem_u32(sm);

    MAINLOOP((2 * DIM) / KS, 2 * DIM, 2 * DIM, g_g, g_lin)

#pragma unroll
    for (int mt = 0; mt < 2; ++mt) {
        int grow = m0 + wm * 32 + mt * 16 + (lane >> 2);
        int p0 = idxp[grow], p1 = idxp[grow + 8];
        int q0 = idxk[grow], q1 = idxk[grow + 8];
#pragma unroll
        for (int nt = 0; nt < 8; ++nt) {
            int gcol = n0 + wn * 64 + nt * 8 + (lane & 3) * 2;
            float2 lb = *reinterpret_cast<const float2*>(lin_b + gcol);
            float2 bs = *reinterpret_cast<const float2*>(bias + gcol);
            float x0 = acc[mt][nt][0] + lb.x;
            float x1 = acc[mt][nt][1] + lb.y;
            float x2 = acc[mt][nt][2] + lb.x;
            float x3 = acc[mt][nt][3] + lb.y;
            x0 = (x0 >= 0.f ? x0 : 0.01f * x0) + bs.x;
            x1 = (x1 >= 0.f ? x1 : 0.01f * x1) + bs.y;
            x2 = (x2 >= 0.f ? x2 : 0.01f * x2) + bs.x;
            x3 = (x3 >= 0.f ? x3 : 0.01f * x3) + bs.y;
            float2 v0; v0.x = x0; v0.y = x1;
            float2 v1; v1.x = x2; v1.y = x3;
            *reinterpret_cast<float2*>(outp + (size_t)p0 * DIM + gcol) = v0;
            *reinterpret_cast<float2*>(outp + (size_t)p1 * DIM + gcol) = v1;
            *reinterpret_cast<float2*>(outk + (size_t)q0 * DIM + gcol) = v0;
            *reinterpret_cast<float2*>(outk + (size_t)q1 * DIM + gcol) = v1;
        }
    }
}

// ---------------------------------------------------------------------------
// Launch
// ---------------------------------------------------------------------------
extern "C" void kernel_launch(void* const* d_in, const int* in_sizes, int n_in,
                              void* d_out, int out_size) {
    const float* h_p  = (const float*)d_in[0];
    const float* h_k  = (const float*)d_in[1];
    const int*   idxp = (const int*)d_in[2];
    const int*   idxk = (const int*)d_in[3];
    // d_in[4] = last_x (unused by the reference computation)
    const float* wo   = (const float*)d_in[5];
    const float* wc   = (const float*)d_in[6];
    const float* lw   = (const float*)d_in[7];
    const float* lb   = (const float*)d_in[8];
    const float* bias = (const float*)d_in[9];
    float* out = (float*)d_out;

    cudaFuncSetAttribute(gemm1_kernel, cudaFuncAttributeMaxDynamicSharedMemorySize, SMEM_BYTES);
    cudaFuncSetAttribute(gemm2_kernel, cudaFuncAttributeMaxDynamicSharedMemorySize, SMEM_BYTES);

    prep_kernel<<<(512 * 1024) / 256, 256>>>(wo, wc, lw);

    inv_fill_kernel<<<MMUT / 256, 256>>>(idxp, idxk);

    split_inputs_kernel<<<dim3((NNODE * DIM / 4) / 256, 2), 256>>>(h_p, h_k);

    gemm1_kernel<<<dim3(DIM / 128, NNODE / 128), 256, SMEM_BYTES>>>(out, 0);
    gemm1_kernel<<<dim3(DIM / 128, NNODE / 128), 256, SMEM_BYTES>>>(out, 1);

    gemm2_kernel<<<dim3(DIM / 128, MMUT / 128), 256, SMEM_BYTES>>>(idxp, idxk, lb, bias, out);
}

// round 16
// speedup vs baseline: 2.5259x; 1.0180x over previous
#include <cuda_runtime.h>
#include <cuda_bf16.h>
#include <cuda_fp16.h>
#include <cstdint>

// ---------------------------------------------------------------------------
// Problem constants
// ---------------------------------------------------------------------------
#define DIM   512
#define NNODE 65536
#define MMUT  32768

// ---------------------------------------------------------------------------
// Smem tile geometry: CTA tile 128x128, K-stage 64, rows padded to 72 halves
// (144 B row stride -> 36 banks mod 32 = 4: ldmatrix 8-row phases conflict-free)
// 2 matrices per stage (A, B), 2-stage ring buffer
// ---------------------------------------------------------------------------
#define KS      64
#define RS      72                    // row stride in 2B elems (144 bytes)
#define MAT_ELE (128 * RS)            // one 128x64(+pad) matrix = 9216 elems
#define BUF_BYTES (2 * MAT_ELE * 2)   // 36864 per stage
#define SMEM_BYTES (2 * BUF_BYTES)    // 73728 (double buffered)

#define DI __device__ __forceinline__

// ---------------------------------------------------------------------------
// Device scratch (__device__ globals only — no allocations)
// ---------------------------------------------------------------------------
__device__ __half g_wo[DIM * DIM];            // [n][k] transposed
__device__ __half g_wc[DIM * DIM];
__device__ __half g_lin[DIM * 2 * DIM];       // [n=512][k=1024]
__device__ __half g_hp[(size_t)NNODE * DIM];
__device__ __half g_hk[(size_t)NNODE * DIM];
__device__ __half g_g[(size_t)MMUT * 2 * DIM];  // gathered+tanh'd GEMM2 A
__device__ int g_inv_p[NNODE];
__device__ int g_inv_k[NNODE];

// ---------------------------------------------------------------------------
// Helpers
// ---------------------------------------------------------------------------
DI uint32_t smem_u32(const void* p) {
    uint32_t a;
    asm("{ .reg .u64 t; cvta.to.shared.u64 t, %1; cvt.u32.u64 %0, t; }"
        : "=r"(a) : "l"(p));
    return a;
}

DI void ldsm_x4(uint32_t* r, uint32_t addr) {
    asm volatile("ldmatrix.sync.aligned.m8n8.x4.shared.b16 {%0,%1,%2,%3}, [%4];"
                 : "=r"(r[0]), "=r"(r[1]), "=r"(r[2]), "=r"(r[3]) : "r"(addr));
}

DI void mma_f16(float* c, const uint32_t* a, uint32_t b0, uint32_t b1) {
    asm volatile(
        "mma.sync.aligned.m16n8k16.row.col.f32.f16.f16.f32 "
        "{%0,%1,%2,%3}, {%4,%5,%6,%7}, {%8,%9}, {%0,%1,%2,%3};"
        : "+f"(c[0]), "+f"(c[1]), "+f"(c[2]), "+f"(c[3])
        : "r"(a[0]), "r"(a[1]), "r"(a[2]), "r"(a[3]), "r"(b0), "r"(b1));
}

DI void cp_async16(uint32_t saddr, const void* gptr) {
    asm volatile("cp.async.cg.shared.global [%0], [%1], 16;"
                 :: "r"(saddr), "l"(gptr));
}
DI void cp_commit() { asm volatile("cp.async.commit_group;" ::: "memory"); }
template <int N> DI void cp_wait() {
    asm volatile("cp.async.wait_group %0;" :: "n"(N) : "memory");
}

// ---------------------------------------------------------------------------
// One K-stage (64): plain fp16, warp tile 32x64, 4 k16 steps.
// Fragment software pipelining: A prefetched one ks ahead (parity ring),
// B prefetched one np ahead (2-slot ring) — every HMMA consumes a fragment
// issued a full block earlier, hiding ldsm latency.
// ---------------------------------------------------------------------------
DI void compute_stage(uint32_t base, int lane, int wm, int wn,
                      float acc[2][8][4]) {
    const uint32_t sA = base;
    const uint32_t sB = base + MAT_ELE * 2;
    const int lrow = lane & 15;
    const int lkh  = lane >> 4;
    const uint32_t kb0 = (uint32_t)(8 * lkh) * 2;

    const uint32_t aAddr0 = sA + (uint32_t)((wm * 32 + lrow) * (RS * 2)) + kb0;
    const uint32_t aAddr1 = aAddr0 + 16 * (RS * 2);
    uint32_t bAddr[4];
#pragma unroll
    for (int np = 0; np < 4; ++np)
        bAddr[np] = sB + (uint32_t)((wn * 64 + np * 16 + lrow) * (RS * 2)) + kb0;

    uint32_t ah[2][2][4];   // [ks parity][mt][frag]
    uint32_t bf[2][4];      // np ring

    // preload ks=0 A fragments and (ks=0, np=0) B fragment
    ldsm_x4(ah[0][0], aAddr0);
    ldsm_x4(ah[0][1], aAddr1);
    ldsm_x4(bf[0], bAddr[0]);

#pragma unroll
    for (int ks = 0; ks < 4; ++ks) {
        const int cur = ks & 1, nxt = cur ^ 1;
        const uint32_t kbN = (uint32_t)((ks + 1) * 16) * 2;
        if (ks < 3) {
            ldsm_x4(ah[nxt][0], aAddr0 + kbN);
            ldsm_x4(ah[nxt][1], aAddr1 + kbN);
        }
#pragma unroll
        for (int np = 0; np < 4; ++np) {
            const int bcur = np & 1, bnxt = bcur ^ 1;
            if (np < 3)
                ldsm_x4(bf[bnxt], bAddr[np + 1] + (uint32_t)(ks * 32));
            else if (ks < 3)
                ldsm_x4(bf[bnxt], bAddr[0] + kbN);
#pragma unroll
            for (int mt = 0; mt < 2; ++mt)
#pragma unroll
                for (int w = 0; w < 2; ++w)
                    mma_f16(acc[mt][np * 2 + w], ah[cur][mt],
                            bf[bcur][w], bf[bcur][w + 2]);
        }
    }
}

// ---------------------------------------------------------------------------
// cp.async one stage: 2 matrices x 128 rows x 128B, 8 chunks of 16B / thread
// ---------------------------------------------------------------------------
DI void stage_cp2(uint32_t sbase, const __half* A, const __half* B,
                  int ldA, int ldB, int m0, int n0, int k0, int tid) {
    const int q = tid & 7;        // 16B chunk within 128B row
    const int r = tid >> 3;       // 0..31
#pragma unroll
    for (int i = 0; i < 8; ++i) {
        const int mat = i >> 2;                   // 0:A 1:B
        const int row = (i & 3) * 32 + r;
        const __half* p = (mat == 0) ? A : B;
        const int ld = (mat == 0) ? ldA : ldB;
        const int r0 = (mat == 0) ? m0 : n0;
        uint32_t sa = sbase + (uint32_t)(mat * (MAT_ELE * 2) + row * (RS * 2) + q * 16);
        cp_async16(sa, p + (size_t)(r0 + row) * ld + k0 + q * 8);
    }
}

// ---------------------------------------------------------------------------
// prep: weights -> fp16 (wo/wc transposed; lin as-is) + inv init
// ---------------------------------------------------------------------------
__global__ void prep_kernel(const float* __restrict__ wo, const float* __restrict__ wc,
                            const float* __restrict__ lw) {
    int i = blockIdx.x * 256 + threadIdx.x;   // 0 .. 512*1024-1
    int n = i >> 10;
    int k = i & 1023;

    g_lin[i] = __float2half_rn(lw[i]);        // lin_w is [512][1024] = [n][k]

    if (k < 512) {
        int src = k * 512 + n;                // B[n][k] = W[k][n]
        int dst = n * 512 + k;
        g_wo[dst] = __float2half_rn(wo[src]);
        g_wc[dst] = __float2half_rn(wc[src]);
    }
    if (i < NNODE) { g_inv_p[i] = -1; g_inv_k[i] = -1; }
}

__global__ void inv_fill_kernel(const int* __restrict__ idxp,
                                const int* __restrict__ idxk) {
    int m = blockIdx.x * 256 + threadIdx.x;   // 0 .. MMUT-1
    g_inv_p[idxp[m]] = m;
    g_inv_k[idxk[m]] = m;
}

// ---------------------------------------------------------------------------
// split inputs: h_p, h_k fp32 -> fp16
// ---------------------------------------------------------------------------
__global__ void split_inputs_kernel(const float* __restrict__ hp,
                                    const float* __restrict__ hk) {
    const size_t idx = (size_t)blockIdx.x * 256 + threadIdx.x;   // float4 index
    const int z = blockIdx.y;
    const float* src = z ? hk : hp;
    __half* dh = z ? g_hk : g_hp;

    float4 v = *reinterpret_cast<const float4*>(src + idx * 4);
    __half2 a; a.x = __float2half_rn(v.x); a.y = __float2half_rn(v.y);
    __half2 b; b.x = __float2half_rn(v.z); b.y = __float2half_rn(v.w);
    uint2 u;
    u.x = *reinterpret_cast<uint32_t*>(&a);
    u.y = *reinterpret_cast<uint32_t*>(&b);
    *reinterpret_cast<uint2*>(dh + idx * 4) = u;
}

// ---------------------------------------------------------------------------
// Mainloop: 2-stage ring, ONE __syncthreads per stage.
// ---------------------------------------------------------------------------
#define MAINLOOP(S, LDA, LDB, Aptr, Bptr)                                       \
    stage_cp2(sb, Aptr, Bptr, LDA, LDB, m0, n0, 0, tid);                        \
    cp_commit();                                                                \
    _Pragma("unroll 1")                                                         \
    for (int s = 0; s < (S); ++s) {                                             \
        cp_wait<0>();                                                           \
        __syncthreads();                                                        \
        if (s + 1 < (S)) {                                                      \
            stage_cp2(sb + ((s + 1) & 1) * BUF_BYTES, Aptr, Bptr,               \
                      LDA, LDB, m0, n0, (s + 1) * KS, tid);                     \
            cp_commit();                                                        \
        }                                                                       \
        compute_stage(sb + (s & 1) * BUF_BYTES, lane, wm, wn, acc);             \
    }

// ---------------------------------------------------------------------------
// GEMM1: trans = h @ W  (plain fp16), both halves in one launch (z dim).
// Fused epilogue: mutual rows -> tanh -> fp16 into g_g; others -> d_out.
// grid (4 n-tiles, 512 m-tiles, 2), block 256, 2 CTAs/SM
// ---------------------------------------------------------------------------
__global__ __launch_bounds__(256, 2) void gemm1_kernel(float* __restrict__ out) {
    extern __shared__ __align__(16) __half sm[];
    const int tid = threadIdx.x, lane = tid & 31, wid = tid >> 5;
    const int wm = wid & 3, wn = wid >> 2;
    const int n0 = blockIdx.x * 128, m0 = blockIdx.y * 128;
    const int z = blockIdx.z;

    const __half* A = z ? g_hk : g_hp;
    const __half* B = z ? g_wc : g_wo;
    const int* inv = z ? g_inv_k : g_inv_p;
    float* dst = out + (size_t)z * NNODE * DIM;
    const int coff = z ? DIM : 0;          // column offset into g (concat)

    float acc[2][8][4];
#pragma unroll
    for (int i = 0; i < 2; ++i)
#pragma unroll
        for (int j = 0; j < 8; ++j)
#pragma unroll
            for (int k = 0; k < 4; ++k) acc[i][j][k] = 0.f;

    const uint32_t sb = smem_u32(sm);

    MAINLOOP(DIM / KS, DIM, DIM, A, B)

    // Epilogue: per accumulator row, route to g (mutual) or d_out (plain)
#pragma unroll
    for (int mt = 0; mt < 2; ++mt) {
#pragma unroll
        for (int r = 0; r < 2; ++r) {
            const int row = m0 + wm * 32 + mt * 16 + (lane >> 2) + r * 8;
            const int m = inv[row];
            if (m >= 0) {
                __half* gp = g_g + (size_t)m * (2 * DIM) + coff;
#pragma unroll
                for (int nt = 0; nt < 8; ++nt) {
                    int gcol = n0 + wn * 64 + nt * 8 + (lane & 3) * 2;
                    __half2 hv;
                    hv.x = __float2half_rn(tanhf(acc[mt][nt][r * 2 + 0]));
                    hv.y = __float2half_rn(tanhf(acc[mt][nt][r * 2 + 1]));
                    *reinterpret_cast<__half2*>(gp + gcol) = hv;
                }
            } else {
                float* rp = dst + (size_t)row * DIM;
#pragma unroll
                for (int nt = 0; nt < 8; ++nt) {
                    int gcol = n0 + wn * 64 + nt * 8 + (lane & 3) * 2;
                    float2 v;
                    v.x = acc[mt][nt][r * 2 + 0];
                    v.y = acc[mt][nt][r * 2 + 1];
                    *reinterpret_cast<float2*>(rp + gcol) = v;
                }
            }
        }
    }
}

// ---------------------------------------------------------------------------
// GEMM2: rows = leaky_relu(g @ lin_w^T + lin_b) + bias, scattered into both
//        halves of d_out.  plain fp16.
// grid (4 n-tiles, 256 m-tiles), block 256, 2 CTAs/SM
// ---------------------------------------------------------------------------
__global__ __launch_bounds__(256, 2) void gemm2_kernel(
    const int* __restrict__ idxp, const int* __restrict__ idxk,
    const float* __restrict__ lin_b, const float* __restrict__ bias,
    float* __restrict__ out) {
    extern __shared__ __align__(16) __half sm[];
    const int tid = threadIdx.x, lane = tid & 31, wid = tid >> 5;
    const int wm = wid & 3, wn = wid >> 2;
    const int n0 = blockIdx.x * 128, m0 = blockIdx.y * 128;

    float* outp = out;
    float* outk = out + (size_t)NNODE * DIM;

    float acc[2][8][4];
#pragma unroll
    for (int i = 0; i < 2; ++i)
#pragma unroll
        for (int j = 0; j < 8; ++j)
#pragma unroll
            for (int k = 0; k < 4; ++k) acc[i][j][k] = 0.f;

    const uint32_t sb = smem_u32(sm);

    MAINLOOP((2 * DIM) / KS, 2 * DIM, 2 * DIM, g_g, g_lin)

#pragma unroll
    for (int mt = 0; mt < 2; ++mt) {
        int grow = m0 + wm * 32 + mt * 16 + (lane >> 2);
        int p0 = idxp[grow], p1 = idxp[grow + 8];
        int q0 = idxk[grow], q1 = idxk[grow + 8];
#pragma unroll
        for (int nt = 0; nt < 8; ++nt) {
            int gcol = n0 + wn * 64 + nt * 8 + (lane & 3) * 2;
            float2 lb = *reinterpret_cast<const float2*>(lin_b + gcol);
            float2 bs = *reinterpret_cast<const float2*>(bias + gcol);
            float x0 = acc[mt][nt][0] + lb.x;
            float x1 = acc[mt][nt][1] + lb.y;
            float x2 = acc[mt][nt][2] + lb.x;
            float x3 = acc[mt][nt][3] + lb.y;
            x0 = (x0 >= 0.f ? x0 : 0.01f * x0) + bs.x;
            x1 = (x1 >= 0.f ? x1 : 0.01f * x1) + bs.y;
            x2 = (x2 >= 0.f ? x2 : 0.01f * x2) + bs.x;
            x3 = (x3 >= 0.f ? x3 : 0.01f * x3) + bs.y;
            float2 v0; v0.x = x0; v0.y = x1;
            float2 v1; v1.x = x2; v1.y = x3;
            *reinterpret_cast<float2*>(outp + (size_t)p0 * DIM + gcol) = v0;
            *reinterpret_cast<float2*>(outp + (size_t)p1 * DIM + gcol) = v1;
            *reinterpret_cast<float2*>(outk + (size_t)q0 * DIM + gcol) = v0;
            *reinterpret_cast<float2*>(outk + (size_t)q1 * DIM + gcol) = v1;
        }
    }
}

// ---------------------------------------------------------------------------
// Launch
// ---------------------------------------------------------------------------
extern "C" void kernel_launch(void* const* d_in, const int* in_sizes, int n_in,
                              void* d_out, int out_size) {
    const float* h_p  = (const float*)d_in[0];
    const float* h_k  = (const float*)d_in[1];
    const int*   idxp = (const int*)d_in[2];
    const int*   idxk = (const int*)d_in[3];
    // d_in[4] = last_x (unused by the reference computation)
    const float* wo   = (const float*)d_in[5];
    const float* wc   = (const float*)d_in[6];
    const float* lw   = (const float*)d_in[7];
    const float* lb   = (const float*)d_in[8];
    const float* bias = (const float*)d_in[9];
    float* out = (float*)d_out;

    cudaFuncSetAttribute(gemm1_kernel, cudaFuncAttributeMaxDynamicSharedMemorySize, SMEM_BYTES);
    cudaFuncSetAttribute(gemm2_kernel, cudaFuncAttributeMaxDynamicSharedMemorySize, SMEM_BYTES);

    prep_kernel<<<(512 * 1024) / 256, 256>>>(wo, wc, lw);

    inv_fill_kernel<<<MMUT / 256, 256>>>(idxp, idxk);

    split_inputs_kernel<<<dim3((NNODE * DIM / 4) / 256, 2), 256>>>(h_p, h_k);

    gemm1_kernel<<<dim3(DIM / 128, NNODE / 128, 2), 256, SMEM_BYTES>>>(out);

    gemm2_kernel<<<dim3(DIM / 128, MMUT / 128), 256, SMEM_BYTES>>>(idxp, idxk, lb, bias, out);
}

// round 17
// speedup vs baseline: 2.5527x; 1.0106x over previous
#include <cuda_runtime.h>
#include <cuda_bf16.h>
#include <cuda_fp16.h>
#include <cstdint>

// ---------------------------------------------------------------------------
// Problem constants
// ---------------------------------------------------------------------------
#define DIM   512
#define NNODE 65536
#define MMUT  32768

// ---------------------------------------------------------------------------
// Smem tile geometry: CTA tile 128x128, K-stage 64, rows padded to 72 halves
// (144 B row stride -> 36 banks mod 32 = 4: ldmatrix 8-row phases conflict-free)
// 2 matrices per stage (A, B), 2-stage ring buffer
// ---------------------------------------------------------------------------
#define KS      64
#define RS      72                    // row stride in 2B elems (144 bytes)
#define MAT_ELE (128 * RS)            // one 128x64(+pad) matrix = 9216 elems
#define BUF_BYTES (2 * MAT_ELE * 2)   // 36864 per stage
#define SMEM_BYTES (2 * BUF_BYTES)    // 73728 (double buffered)

#define DI __device__ __forceinline__

// ---------------------------------------------------------------------------
// Device scratch (__device__ globals only — no allocations)
// ---------------------------------------------------------------------------
__device__ __half g_wo[DIM * DIM];            // [n][k] transposed
__device__ __half g_wc[DIM * DIM];
__device__ __half g_lin[DIM * 2 * DIM];       // [n=512][k=1024]
__device__ __half g_hp[(size_t)NNODE * DIM];
__device__ __half g_hk[(size_t)NNODE * DIM];
__device__ __half g_g[(size_t)MMUT * 2 * DIM];  // gathered+tanh'd GEMM2 A
__device__ int g_inv_p[NNODE];
__device__ int g_inv_k[NNODE];

// ---------------------------------------------------------------------------
// Helpers
// ---------------------------------------------------------------------------
DI uint32_t smem_u32(const void* p) {
    uint32_t a;
    asm("{ .reg .u64 t; cvta.to.shared.u64 t, %1; cvt.u32.u64 %0, t; }"
        : "=r"(a) : "l"(p));
    return a;
}

DI void ldsm_x4(uint32_t* r, uint32_t addr) {
    asm volatile("ldmatrix.sync.aligned.m8n8.x4.shared.b16 {%0,%1,%2,%3}, [%4];"
                 : "=r"(r[0]), "=r"(r[1]), "=r"(r[2]), "=r"(r[3]) : "r"(addr));
}

DI void mma_f16(float* c, const uint32_t* a, uint32_t b0, uint32_t b1) {
    asm volatile(
        "mma.sync.aligned.m16n8k16.row.col.f32.f16.f16.f32 "
        "{%0,%1,%2,%3}, {%4,%5,%6,%7}, {%8,%9}, {%0,%1,%2,%3};"
        : "+f"(c[0]), "+f"(c[1]), "+f"(c[2]), "+f"(c[3])
        : "r"(a[0]), "r"(a[1]), "r"(a[2]), "r"(a[3]), "r"(b0), "r"(b1));
}

DI void cp_async16(uint32_t saddr, const void* gptr) {
    asm volatile("cp.async.cg.shared.global [%0], [%1], 16;"
                 :: "r"(saddr), "l"(gptr));
}
DI void cp_commit() { asm volatile("cp.async.commit_group;" ::: "memory"); }
template <int N> DI void cp_wait() {
    asm volatile("cp.async.wait_group %0;" :: "n"(N) : "memory");
}

// ---------------------------------------------------------------------------
// One K-stage (64): plain fp16, warp tile 32x64, 4 k16 steps.
// Fragment software pipelining (A one ks ahead, B one np ahead).
// ---------------------------------------------------------------------------
DI void compute_stage(uint32_t base, int lane, int wm, int wn,
                      float acc[2][8][4]) {
    const uint32_t sA = base;
    const uint32_t sB = base + MAT_ELE * 2;
    const int lrow = lane & 15;
    const int lkh  = lane >> 4;
    const uint32_t kb0 = (uint32_t)(8 * lkh) * 2;

    const uint32_t aAddr0 = sA + (uint32_t)((wm * 32 + lrow) * (RS * 2)) + kb0;
    const uint32_t aAddr1 = aAddr0 + 16 * (RS * 2);
    uint32_t bAddr[4];
#pragma unroll
    for (int np = 0; np < 4; ++np)
        bAddr[np] = sB + (uint32_t)((wn * 64 + np * 16 + lrow) * (RS * 2)) + kb0;

    uint32_t ah[2][2][4];   // [ks parity][mt][frag]
    uint32_t bf[2][4];      // np ring

    ldsm_x4(ah[0][0], aAddr0);
    ldsm_x4(ah[0][1], aAddr1);
    ldsm_x4(bf[0], bAddr[0]);

#pragma unroll
    for (int ks = 0; ks < 4; ++ks) {
        const int cur = ks & 1, nxt = cur ^ 1;
        const uint32_t kbN = (uint32_t)((ks + 1) * 16) * 2;
        if (ks < 3) {
            ldsm_x4(ah[nxt][0], aAddr0 + kbN);
            ldsm_x4(ah[nxt][1], aAddr1 + kbN);
        }
#pragma unroll
        for (int np = 0; np < 4; ++np) {
            const int bcur = np & 1, bnxt = bcur ^ 1;
            if (np < 3)
                ldsm_x4(bf[bnxt], bAddr[np + 1] + (uint32_t)(ks * 32));
            else if (ks < 3)
                ldsm_x4(bf[bnxt], bAddr[0] + kbN);
#pragma unroll
            for (int mt = 0; mt < 2; ++mt)
#pragma unroll
                for (int w = 0; w < 2; ++w)
                    mma_f16(acc[mt][np * 2 + w], ah[cur][mt],
                            bf[bcur][w], bf[bcur][w + 2]);
        }
    }
}

// ---------------------------------------------------------------------------
// cp.async one stage from precomputed per-thread pointers.
// LDA/LDB are compile-time: all offsets fold to constants + k0.
// ---------------------------------------------------------------------------
template <int LDA, int LDB>
DI void stage_cp2(uint32_t sA, uint32_t sB,
                  const __half* pA, const __half* pB, int k0) {
#pragma unroll
    for (int g = 0; g < 4; ++g) {
        cp_async16(sA + (uint32_t)(g * 32 * (RS * 2)), pA + (size_t)(g * 32 * LDA) + k0);
        cp_async16(sB + (uint32_t)(g * 32 * (RS * 2)), pB + (size_t)(g * 32 * LDB) + k0);
    }
}

// ---------------------------------------------------------------------------
// prep: weights -> fp16 (wo/wc transposed; lin as-is) + inv init
// ---------------------------------------------------------------------------
__global__ void prep_kernel(const float* __restrict__ wo, const float* __restrict__ wc,
                            const float* __restrict__ lw) {
    int i = blockIdx.x * 256 + threadIdx.x;   // 0 .. 512*1024-1
    int n = i >> 10;
    int k = i & 1023;

    g_lin[i] = __float2half_rn(lw[i]);        // lin_w is [512][1024] = [n][k]

    if (k < 512) {
        int src = k * 512 + n;                // B[n][k] = W[k][n]
        int dst = n * 512 + k;
        g_wo[dst] = __float2half_rn(wo[src]);
        g_wc[dst] = __float2half_rn(wc[src]);
    }
    if (i < NNODE) { g_inv_p[i] = -1; g_inv_k[i] = -1; }
}

__global__ void inv_fill_kernel(const int* __restrict__ idxp,
                                const int* __restrict__ idxk) {
    int m = blockIdx.x * 256 + threadIdx.x;   // 0 .. MMUT-1
    g_inv_p[idxp[m]] = m;
    g_inv_k[idxk[m]] = m;
}

// ---------------------------------------------------------------------------
// split inputs: h_p, h_k fp32 -> fp16
// ---------------------------------------------------------------------------
__global__ void split_inputs_kernel(const float* __restrict__ hp,
                                    const float* __restrict__ hk) {
    const size_t idx = (size_t)blockIdx.x * 256 + threadIdx.x;   // float4 index
    const int z = blockIdx.y;
    const float* src = z ? hk : hp;
    __half* dh = z ? g_hk : g_hp;

    float4 v = *reinterpret_cast<const float4*>(src + idx * 4);
    __half2 a; a.x = __float2half_rn(v.x); a.y = __float2half_rn(v.y);
    __half2 b; b.x = __float2half_rn(v.z); b.y = __float2half_rn(v.w);
    uint2 u;
    u.x = *reinterpret_cast<uint32_t*>(&a);
    u.y = *reinterpret_cast<uint32_t*>(&b);
    *reinterpret_cast<uint2*>(dh + idx * 4) = u;
}

// ---------------------------------------------------------------------------
// Mainloop: 2-stage ring, ONE __syncthreads per stage, hoisted addressing.
// ---------------------------------------------------------------------------
#define MAINLOOP(S, LDA, LDB, Aptr, Bptr)                                       \
    {                                                                           \
        const int qq = tid & 7, rr = tid >> 3;                                  \
        const __half* pA = (Aptr) + (size_t)(m0 + rr) * (LDA) + qq * 8;         \
        const __half* pB = (Bptr) + (size_t)(n0 + rr) * (LDB) + qq * 8;         \
        const uint32_t sA0 = sb + (uint32_t)(rr * (RS * 2) + qq * 16);          \
        const uint32_t sB0 = sA0 + MAT_ELE * 2;                                 \
        stage_cp2<LDA, LDB>(sA0, sB0, pA, pB, 0);                               \
        cp_commit();                                                            \
        _Pragma("unroll 1")                                                     \
        for (int s = 0; s < (S); ++s) {                                         \
            cp_wait<0>();                                                       \
            __syncthreads();                                                    \
            if (s + 1 < (S)) {                                                  \
                uint32_t boff = ((s + 1) & 1) * BUF_BYTES;                      \
                stage_cp2<LDA, LDB>(sA0 + boff, sB0 + boff, pA, pB,             \
                                    (s + 1) * KS);                              \
                cp_commit();                                                    \
            }                                                                   \
            compute_stage(sb + (s & 1) * BUF_BYTES, lane, wm, wn, acc);         \
        }                                                                       \
    }

// ---------------------------------------------------------------------------
// GEMM1: trans = h @ W  (plain fp16), both halves in one launch (z dim).
// Fused epilogue: mutual rows -> tanh -> fp16 into g_g; others -> d_out.
// grid (4 n-tiles, 512 m-tiles, 2), block 256, 2 CTAs/SM
// ---------------------------------------------------------------------------
__global__ __launch_bounds__(256, 2) void gemm1_kernel(float* __restrict__ out) {
    extern __shared__ __align__(16) __half sm[];
    const int tid = threadIdx.x, lane = tid & 31, wid = tid >> 5;
    const int wm = wid & 3, wn = wid >> 2;
    const int n0 = blockIdx.x * 128, m0 = blockIdx.y * 128;
    const int z = blockIdx.z;

    const __half* A = z ? g_hk : g_hp;
    const __half* B = z ? g_wc : g_wo;
    const int* inv = z ? g_inv_k : g_inv_p;
    float* dst = out + (size_t)z * NNODE * DIM;
    const int coff = z ? DIM : 0;          // column offset into g (concat)

    float acc[2][8][4];
#pragma unroll
    for (int i = 0; i < 2; ++i)
#pragma unroll
        for (int j = 0; j < 8; ++j)
#pragma unroll
            for (int k = 0; k < 4; ++k) acc[i][j][k] = 0.f;

    const uint32_t sb = smem_u32(sm);

    MAINLOOP(DIM / KS, DIM, DIM, A, B)

    // Epilogue: per accumulator row, route to g (mutual) or d_out (plain)
#pragma unroll
    for (int mt = 0; mt < 2; ++mt) {
#pragma unroll
        for (int r = 0; r < 2; ++r) {
            const int row = m0 + wm * 32 + mt * 16 + (lane >> 2) + r * 8;
            const int m = inv[row];
            if (m >= 0) {
                __half* gp = g_g + (size_t)m * (2 * DIM) + coff;
#pragma unroll
                for (int nt = 0; nt < 8; ++nt) {
                    int gcol = n0 + wn * 64 + nt * 8 + (lane & 3) * 2;
                    __half2 hv;
                    hv.x = __float2half_rn(tanhf(acc[mt][nt][r * 2 + 0]));
                    hv.y = __float2half_rn(tanhf(acc[mt][nt][r * 2 + 1]));
                    *reinterpret_cast<__half2*>(gp + gcol) = hv;
                }
            } else {
                float* rp = dst + (size_t)row * DIM;
#pragma unroll
                for (int nt = 0; nt < 8; ++nt) {
                    int gcol = n0 + wn * 64 + nt * 8 + (lane & 3) * 2;
                    float2 v;
                    v.x = acc[mt][nt][r * 2 + 0];
                    v.y = acc[mt][nt][r * 2 + 1];
                    *reinterpret_cast<float2*>(rp + gcol) = v;
                }
            }
        }
    }
}

// ---------------------------------------------------------------------------
// GEMM2: rows = leaky_relu(g @ lin_w^T + lin_b) + bias, scattered into both
//        halves of d_out.  plain fp16.
// grid (4 n-tiles, 256 m-tiles), block 256, 2 CTAs/SM
// ---------------------------------------------------------------------------
__global__ __launch_bounds__(256, 2) void gemm2_kernel(
    const int* __restrict__ idxp, const int* __restrict__ idxk,
    const float* __restrict__ lin_b, const float* __restrict__ bias,
    float* __restrict__ out) {
    extern __shared__ __align__(16) __half sm[];
    const int tid = threadIdx.x, lane = tid & 31, wid = tid >> 5;
    const int wm = wid & 3, wn = wid >> 2;
    const int n0 = blockIdx.x * 128, m0 = blockIdx.y * 128;

    float* outp = out;
    float* outk = out + (size_t)NNODE * DIM;

    float acc[2][8][4];
#pragma unroll
    for (int i = 0; i < 2; ++i)
#pragma unroll
        for (int j = 0; j < 8; ++j)
#pragma unroll
            for (int k = 0; k < 4; ++k) acc[i][j][k] = 0.f;

    const uint32_t sb = smem_u32(sm);

    MAINLOOP((2 * DIM) / KS, 2 * DIM, 2 * DIM, g_g, g_lin)

#pragma unroll
    for (int mt = 0; mt < 2; ++mt) {
        int grow = m0 + wm * 32 + mt * 16 + (lane >> 2);
        int p0 = idxp[grow], p1 = idxp[grow + 8];
        int q0 = idxk[grow], q1 = idxk[grow + 8];
#pragma unroll
        for (int nt = 0; nt < 8; ++nt) {
            int gcol = n0 + wn * 64 + nt * 8 + (lane & 3) * 2;
            float2 lb = *reinterpret_cast<const float2*>(lin_b + gcol);
            float2 bs = *reinterpret_cast<const float2*>(bias + gcol);
            float x0 = acc[mt][nt][0] + lb.x;
            float x1 = acc[mt][nt][1] + lb.y;
            float x2 = acc[mt][nt][2] + lb.x;
            float x3 = acc[mt][nt][3] + lb.y;
            x0 = (x0 >= 0.f ? x0 : 0.01f * x0) + bs.x;
            x1 = (x1 >= 0.f ? x1 : 0.01f * x1) + bs.y;
            x2 = (x2 >= 0.f ? x2 : 0.01f * x2) + bs.x;
            x3 = (x3 >= 0.f ? x3 : 0.01f * x3) + bs.y;
            float2 v0; v0.x = x0; v0.y = x1;
            float2 v1; v1.x = x2; v1.y = x3;
            *reinterpret_cast<float2*>(outp + (size_t)p0 * DIM + gcol) = v0;
            *reinterpret_cast<float2*>(outp + (size_t)p1 * DIM + gcol) = v1;
            *reinterpret_cast<float2*>(outk + (size_t)q0 * DIM + gcol) = v0;
            *reinterpret_cast<float2*>(outk + (size_t)q1 * DIM + gcol) = v1;
        }
    }
}

// ---------------------------------------------------------------------------
// Launch
// ---------------------------------------------------------------------------
extern "C" void kernel_launch(void* const* d_in, const int* in_sizes, int n_in,
                              void* d_out, int out_size) {
    const float* h_p  = (const float*)d_in[0];
    const float* h_k  = (const float*)d_in[1];
    const int*   idxp = (const int*)d_in[2];
    const int*   idxk = (const int*)d_in[3];
    // d_in[4] = last_x (unused by the reference computation)
    const float* wo   = (const float*)d_in[5];
    const float* wc   = (const float*)d_in[6];
    const float* lw   = (const float*)d_in[7];
    const float* lb   = (const float*)d_in[8];
    const float* bias = (const float*)d_in[9];
    float* out = (float*)d_out;

    cudaFuncSetAttribute(gemm1_kernel, cudaFuncAttributeMaxDynamicSharedMemorySize, SMEM_BYTES);
    cudaFuncSetAttribute(gemm2_kernel, cudaFuncAttributeMaxDynamicSharedMemorySize, SMEM_BYTES);

    prep_kernel<<<(512 * 1024) / 256, 256>>>(wo, wc, lw);

    inv_fill_kernel<<<MMUT / 256, 256>>>(idxp, idxk);

    split_inputs_kernel<<<dim3((NNODE * DIM / 4) / 256, 2), 256>>>(h_p, h_k);

    gemm1_kernel<<<dim3(DIM / 128, NNODE / 128, 2), 256, SMEM_BYTES>>>(out);

    gemm2_kernel<<<dim3(DIM / 128, MMUT / 128), 256, SMEM_BYTES>>>(idxp, idxk, lb, bias, out);
}